// round 13
// baseline (speedup 1.0000x reference)
#include <cuda_runtime.h>
#include <cuda_bf16.h>
#include <cstdint>
#include <cstddef>

using bf16  = __nv_bfloat16;
using bf162 = __nv_bfloat162;

#define BATCH  4
#define NTOK   4096
#define CDIM   256
#define GROUPS 8
#define EPSV   1e-3f
#define GNM    131072.0f     // elements per (b,g) group
#define NSPLIT 56            // key blocks for big CTAs; small = 64 - NSPLIT

// q pre-scale: (1/16 softmax scale) * log2(e) so exp(x) == exp2(s)
#define QSCALE 0.09016843806266f

// ---------------- static device scratch (no cudaMalloc) ---------------------
__device__ bf16  g_qkv  [(size_t)BATCH * NTOK * 3 * CDIM];
__device__ bf16  g_wt   [3 * CDIM * CDIM];
__device__ bf16  g_wpt  [CDIM * CDIM];
__device__ float g_b3   [3 * CDIM];
__device__ float g_part [BATCH * GROUPS * 32 * 2];  // partial sums
__device__ float g_po   [(size_t)128 * 32768];      // split-K partial O (16MB)
__device__ float g_pl   [128 * 512];                // split-K partial l
__device__ int   g_flag [128];                      // split-K ready flags

// ---------------- helpers -----------------------------------------------------
__device__ __forceinline__ uint32_t smem_u32(const void* p) {
    uint32_t a;
    asm("{ .reg .u64 t; cvta.to.shared.u64 t, %1; cvt.u32.u64 %0, t; }"
        : "=r"(a) : "l"(p));
    return a;
}
__device__ __forceinline__ uint32_t swz(uint32_t b) { return b ^ ((b >> 3) & 0x70); }

#define LDM4(r, addr) \
    asm volatile("ldmatrix.sync.aligned.m8n8.x4.shared.b16 {%0,%1,%2,%3}, [%4];" \
        : "=r"((r)[0]), "=r"((r)[1]), "=r"((r)[2]), "=r"((r)[3]) : "r"(addr))
#define LDM4T(r, addr) \
    asm volatile("ldmatrix.sync.aligned.m8n8.x4.trans.shared.b16 {%0,%1,%2,%3}, [%4];" \
        : "=r"((r)[0]), "=r"((r)[1]), "=r"((r)[2]), "=r"((r)[3]) : "r"(addr))

__device__ __forceinline__ void mma_bf16(float* c, const uint32_t* a,
                                         uint32_t b0, uint32_t b1) {
    asm volatile(
        "mma.sync.aligned.m16n8k16.row.col.f32.bf16.bf16.f32 "
        "{%0,%1,%2,%3}, {%4,%5,%6,%7}, {%8,%9}, {%0,%1,%2,%3};"
        : "+f"(c[0]), "+f"(c[1]), "+f"(c[2]), "+f"(c[3])
        : "r"(a[0]), "r"(a[1]), "r"(a[2]), "r"(a[3]), "r"(b0), "r"(b1));
}

__device__ __forceinline__ void cp16(uint32_t saddr, const void* gaddr) {
    asm volatile("cp.async.cg.shared.global [%0], [%1], 16;"
                 :: "r"(saddr), "l"(gaddr));
}
__device__ __forceinline__ void cp_commit() {
    asm volatile("cp.async.commit_group;" ::: "memory");
}
__device__ __forceinline__ void cp_wait1() {
    asm volatile("cp.async.wait_group 1;" ::: "memory");
}
__device__ __forceinline__ void cp_wait0() {
    asm volatile("cp.async.wait_group 0;" ::: "memory");
}
__device__ __forceinline__ uint32_t packbf(float a, float b) {
    bf162 p = __floats2bfloat162_rn(a, b);
    return *(uint32_t*)&p;
}
__device__ __forceinline__ float ex2(float x) {
    float r;
    asm("ex2.approx.f32 %0, %1;" : "=f"(r) : "f"(x));
    return r;
}
__device__ __forceinline__ void sts64(uint32_t a, uint32_t v0, uint32_t v1) {
    asm volatile("st.shared.v2.b32 [%0], {%1,%2};" :: "r"(a), "r"(v0), "r"(v1));
}
__device__ __forceinline__ uint32_t ld_acquire(const int* p) {
    uint32_t v;
    asm volatile("ld.acquire.gpu.global.b32 %0, [%1];" : "=r"(v) : "l"(p));
    return v;
}
__device__ __forceinline__ void st_release(int* p, int v) {
    asm volatile("st.release.gpu.global.b32 [%0], %1;" :: "l"(p), "r"(v));
}

// ---- per-CTA GroupNorm stats: 8 warps reduce 32 partials each -> sstat[8] ----
__device__ __forceinline__ void compute_stats(const float* __restrict__ part,
                                              int b, int wid, int lane,
                                              float2* sstat)
{
    const float2 p = *(const float2*)&part[(((b << 3) + wid) * 32 + lane) * 2];
    float s = p.x, ss = p.y;
    #pragma unroll
    for (int o = 16; o; o >>= 1) {
        s  += __shfl_xor_sync(0xffffffffu, s,  o);
        ss += __shfl_xor_sync(0xffffffffu, ss, o);
    }
    if (lane == 0) {
        const float mean = s / GNM;
        sstat[wid] = make_float2(mean, rsqrtf(ss / GNM - mean * mean + EPSV));
    }
}

// ---------------- merged: weight prep (256 blocks) + GN partial (1024) -------
__global__ void __launch_bounds__(256)
prep_gn_kernel(const float* __restrict__ Wq, const float* __restrict__ Wk,
               const float* __restrict__ Wv, const float* __restrict__ Wp,
               bf16* __restrict__ wt, bf16* __restrict__ wpt,
               const float* __restrict__ bq, const float* __restrict__ bk,
               const float* __restrict__ bv, float* __restrict__ b3,
               const float* __restrict__ x, float* __restrict__ part)
{
    const int tid = threadIdx.x;
    if (blockIdx.x < 1024) {
        // ---- GN partial sums ----
        const int bg = blockIdx.x >> 5, slab = blockIdx.x & 31;
        const int b = bg >> 3, g = bg & 7;
        const size_t base = (size_t)b * NTOK * CDIM + (size_t)g * 32 +
                            (size_t)(slab * 128) * CDIM;

        float s = 0.f, ss = 0.f;
        #pragma unroll
        for (int i = tid; i < 128 * 8; i += 256) {
            const int m = i >> 3, qd = i & 7;
            float4 v = *(const float4*)&x[base + (size_t)m * CDIM + qd * 4];
            s  += v.x + v.y + v.z + v.w;
            ss += v.x * v.x + v.y * v.y + v.z * v.z + v.w * v.w;
        }
        #pragma unroll
        for (int o = 16; o; o >>= 1) {
            s  += __shfl_xor_sync(0xffffffffu, s,  o);
            ss += __shfl_xor_sync(0xffffffffu, ss, o);
        }
        __shared__ float shs[8], shss[8];
        if (!(tid & 31)) { shs[tid >> 5] = s; shss[tid >> 5] = ss; }
        __syncthreads();
        if (tid == 0) {
            float st = 0.f, sst = 0.f;
            #pragma unroll
            for (int i = 0; i < 8; i++) { st += shs[i]; sst += shss[i]; }
            part[blockIdx.x * 2]     = st;
            part[blockIdx.x * 2 + 1] = sst;
        }
    } else {
        // ---- weight transpose + convert ----
        const int idx = blockIdx.x - 1024;
        const int z = idx >> 6;
        const int bxq = (idx & 7) * 32, byq = ((idx >> 3) & 7) * 32;
        const float* W = (z == 0) ? Wq : (z == 1) ? Wk : (z == 2) ? Wv : Wp;
        bf16* out = (z < 3) ? (wt + (size_t)z * CDIM * CDIM) : wpt;
        const float scale = (z == 0) ? QSCALE : 1.0f;

        __shared__ float t[32][33];
        const int tx = tid & 31, ty = tid >> 5;
        for (int yy = ty; yy < 32; yy += 8)
            t[yy][tx] = W[(size_t)(byq + yy) * CDIM + bxq + tx];
        __syncthreads();
        for (int yy = ty; yy < 32; yy += 8)
            out[(size_t)(bxq + yy) * CDIM + byq + tx] =
                __float2bfloat16(t[tx][yy] * scale);

        if (z == 3 && idx == 192) {   // z==3, x==0, y==0
            for (int j = tid; j < 768; j += 256)
                b3[j] = (j < 256) ? bq[j] * QSCALE
                      : (j < 512) ? bk[j - 256] : bv[j - 512];
            if (tid < 128) g_flag[tid] = 0;   // reset split-K flags
        }
    }
}

// ---------------- QKV GEMM with inline GroupNorm on A (R10 proven shape) -----
#define QSM (1024 + 65536 + 32768)

__device__ __forceinline__ void cpb_tile(uint32_t sdst,
    const bf16* __restrict__ g, int row0, int k0, int tid)
{
    #pragma unroll
    for (int l = 0; l < 4; ++l) {
        const int f = tid + l * 256;
        const int r = f >> 3;
        const int q = f & 7;
        cp16(sdst + swz((uint32_t)(r * 128 + q * 16)),
             g + (size_t)(row0 + r) * 256 + k0 + q * 8);
    }
}

__global__ void __launch_bounds__(256)
qkv_gemm(const float* __restrict__ x, const float* __restrict__ gamma,
         const float* __restrict__ beta, const float* __restrict__ part,
         const bf16* __restrict__ wt, const float* __restrict__ b3,
         bf16* __restrict__ C)
{
    extern __shared__ char smraw[];
    const uint32_t base = (smem_u32(smraw) + 1023u) & ~1023u;
    const uint32_t As = base;              // 64KB: 4 panels of 128x64 cols
    const uint32_t Bs = base + 65536u;     // 2x16KB B double buffer
    __shared__ float2 sstat[8];

    const int tid  = threadIdx.x;
    const int wid  = tid >> 5;
    const int lane = tid & 31;
    const int wm   = wid & 3;
    const int wn   = wid >> 2;
    const int row0 = blockIdx.y * 128;
    const int b    = row0 >> 12;
    const int col0 = blockIdx.x * 128;

    compute_stats(part, b, wid, lane, sstat);
    cpb_tile(Bs, wt, col0, 0, tid);
    cp_commit();
    __syncthreads();   // sstat visible

    // A: load x fp32, normalize, pack bf16, store to panel-format smem
    #pragma unroll
    for (int l = 0; l < 32; ++l) {
        const int f  = tid + l * 256;
        const int r  = f >> 6;
        const int c4 = f & 63;
        float4 xv = *(const float4*)&x[(size_t)(row0 + r) * 256 + c4 * 4];
        float4 gm = *(const float4*)&gamma[c4 * 4];
        float4 bt = *(const float4*)&beta [c4 * 4];
        const float2 st = sstat[c4 >> 3];
        const uint32_t u0 = packbf((xv.x - st.x) * st.y * gm.x + bt.x,
                                   (xv.y - st.x) * st.y * gm.y + bt.y);
        const uint32_t u1 = packbf((xv.z - st.x) * st.y * gm.z + bt.z,
                                   (xv.w - st.x) * st.y * gm.w + bt.w);
        sts64(As + (uint32_t)(c4 >> 4) * 16384u +
                  swz((uint32_t)(r * 128 + (c4 & 15) * 8)), u0, u1);
    }

    const int arow  = wm * 32 + (lane & 15);
    const int brow  = wn * 64 + (lane & 15);
    const int colb  = (lane >> 4) * 16;

    float acc[2][8][4];
    #pragma unroll
    for (int i = 0; i < 2; i++)
        #pragma unroll
        for (int j = 0; j < 8; j++)
            #pragma unroll
            for (int q = 0; q < 4; q++) acc[i][j][q] = 0.f;

    for (int i = 0; i < 4; ++i) {
        if (i + 1 < 4) {
            cpb_tile(Bs + (uint32_t)((i + 1) & 1) * 16384u,
                     wt, col0, (i + 1) * 64, tid);
            cp_commit();
            cp_wait1();
        } else {
            cp_wait0();
        }
        __syncthreads();

        const uint32_t ap = As + (uint32_t)i * 16384u;
        const uint32_t bb = Bs + (uint32_t)(i & 1) * 16384u;
        #pragma unroll
        for (int kst = 0; kst < 4; ++kst) {
            const uint32_t kb = (uint32_t)(kst * 32 + colb);
            uint32_t afr[2][4], bfr[4][4];
            LDM4(afr[0], ap + swz((uint32_t)(arow)      * 128 + kb));
            LDM4(afr[1], ap + swz((uint32_t)(arow + 16) * 128 + kb));
            #pragma unroll
            for (int nb2 = 0; nb2 < 4; ++nb2)
                LDM4(bfr[nb2], bb + swz((uint32_t)(brow + nb2 * 16) * 128 + kb));
            #pragma unroll
            for (int ma = 0; ma < 2; ++ma)
                #pragma unroll
                for (int nb2 = 0; nb2 < 4; ++nb2) {
                    mma_bf16(acc[ma][nb2 * 2],     afr[ma], bfr[nb2][0], bfr[nb2][2]);
                    mma_bf16(acc[ma][nb2 * 2 + 1], afr[ma], bfr[nb2][1], bfr[nb2][3]);
                }
        }
        __syncthreads();
    }

    #pragma unroll
    for (int ma = 0; ma < 2; ++ma) {
        const size_t r0 = (size_t)(row0 + wm * 32 + ma * 16 + (lane >> 2));
        #pragma unroll
        for (int na = 0; na < 8; ++na) {
            const int cc = col0 + wn * 64 + (na >> 1) * 16 + (na & 1) * 8 +
                           (lane & 3) * 2;
            const float b0 = b3[cc], b1 = b3[cc + 1];
            *(uint32_t*)(C + r0 * 768 + cc) =
                packbf(acc[ma][na][0] + b0, acc[ma][na][1] + b1);
            *(uint32_t*)(C + (r0 + 8) * 768 + cc) =
                packbf(acc[ma][na][2] + b0, acc[ma][na][3] + b1);
        }
    }
}

// ---------------- fused flash attention, key-split + output projection -------
// 256 CTAs: blocks 0-127 ("big") do key blocks [0,NSPLIT) for tile bid; blocks
// 128-255 ("small") do [NSPLIT,64) for tile bid-128, dump raw (O,l) partials +
// release flag, exit. Big overlaps Wp staging with an acquire-spin, combines,
// then runs the proven proj + GN-residual epilogue. No-max softmax => partials
// combine by pure addition (exact fp32).
#define FSM (1024 + 196608)

__global__ void __launch_bounds__(256, 1)
flash_kernel(const bf16* __restrict__ qkv, const bf16* __restrict__ wpt,
             const float* __restrict__ bp, const float* __restrict__ x,
             const float* __restrict__ part, const float* __restrict__ gamma,
             const float* __restrict__ beta, float* __restrict__ out)
{
    extern __shared__ char smraw[];
    const uint32_t base = (smem_u32(smraw) + 1023u) & ~1023u;
    const uint32_t Qs  = base;                 // 64KB Q
    const uint32_t Ks  = base + 65536u;        // 64KB K 2 stages
    const uint32_t Vs  = base + 131072u;       // 64KB V 2 stages
    const uint32_t Wps = base + 65536u;        // epilogue: Wp^T 128KB over K+V
    __shared__ float2 sstat[8];

    const int tid   = threadIdx.x;
    const int wid   = tid >> 5;
    const int lane  = tid & 31;
    const int bid   = blockIdx.x;
    const int big   = (bid < 128);
    const int tile  = bid & 127;
    const int b     = tile >> 5;
    const int q0    = (tile & 31) * 128;
    const int jbase = big ? 0 : NSPLIT;
    const int nblk  = big ? NSPLIT : (64 - NSPLIT);
    const bf16* qp = qkv + (size_t)b * NTOK * 768;
    const bf16* kp = qp + 256;
    const bf16* vp = qp + 512;

    #pragma unroll
    for (int l = 0; l < 16; ++l) {
        const int f = tid + l * 256;
        const int r = f >> 5, pan = (f >> 3) & 3, ch = f & 7;
        cp16(Qs + pan * 16384u + swz((uint32_t)(r * 128 + ch * 16)),
             qp + (size_t)(q0 + r) * 768 + pan * 64 + ch * 8);
    }
    #pragma unroll
    for (int l = 0; l < 8; ++l) {
        const int f = tid + l * 256;
        const int r = f >> 5, pan = (f >> 3) & 3, ch = f & 7;
        const uint32_t so = (uint32_t)pan * 8192u + swz((uint32_t)(r * 128 + ch * 16));
        cp16(Ks + so, kp + (size_t)(jbase * 64 + r) * 768 + pan * 64 + ch * 8);
        cp16(Vs + so, vp + (size_t)(jbase * 64 + r) * 768 + pan * 64 + ch * 8);
    }
    cp_commit();

    compute_stats(part, b, wid, lane, sstat);

    const int l15  = lane & 15;
    const int arow = wid * 16 + l15;
    const int colb = (lane >> 4) * 16;
    const int keyl = ((lane >> 3) & 1) * 8 + (lane & 7);
    const int dl8  = (lane >> 4) * 8;

    float acc_o[32][4];
    #pragma unroll
    for (int n = 0; n < 32; ++n)
        #pragma unroll
        for (int q = 0; q < 4; ++q) acc_o[n][q] = 0.f;
    float l0 = 0.f, l1 = 0.f;

    for (int j = 0; j < nblk; ++j) {
        const uint32_t st = (uint32_t)(j & 1) * 32768u;

        __syncthreads();   // stage (j+1)&1 fully consumed (iter j-1)
        if (j + 1 < nblk) {
            const uint32_t stn = (uint32_t)((j + 1) & 1) * 32768u;
            const int key0 = (jbase + j + 1) * 64;
            #pragma unroll
            for (int l = 0; l < 8; ++l) {
                const int f = tid + l * 256;
                const int r = f >> 5, pan = (f >> 3) & 3, ch = f & 7;
                const uint32_t so = (uint32_t)pan * 8192u +
                                    swz((uint32_t)(r * 128 + ch * 16));
                cp16(Ks + stn + so, kp + (size_t)(key0 + r) * 768 + pan * 64 + ch * 8);
                cp16(Vs + stn + so, vp + (size_t)(key0 + r) * 768 + pan * 64 + ch * 8);
            }
            cp_commit();
            cp_wait1();
        } else {
            cp_wait0();
        }

        // ---- S = Q @ K^T ----
        float s[8][4];
        #pragma unroll
        for (int n = 0; n < 8; ++n)
            #pragma unroll
            for (int q = 0; q < 4; ++q) s[n][q] = 0.f;

        #pragma unroll
        for (int pan = 0; pan < 4; ++pan) {
            const uint32_t qb = Qs + (uint32_t)pan * 16384u;
            const uint32_t kb = Ks + st + (uint32_t)pan * 8192u;
            #pragma unroll
            for (int kst = 0; kst < 4; ++kst) {
                const uint32_t kby = (uint32_t)(kst * 32 + colb);
                uint32_t afr[4], bfr[4][4];
                LDM4(afr, qb + swz((uint32_t)arow * 128 + kby));
                #pragma unroll
                for (int nb2 = 0; nb2 < 4; ++nb2)
                    LDM4(bfr[nb2], kb + swz((uint32_t)(l15 + nb2 * 16) * 128 + kby));
                #pragma unroll
                for (int nb2 = 0; nb2 < 4; ++nb2) {
                    mma_bf16(s[nb2 * 2],     afr, bfr[nb2][0], bfr[nb2][2]);
                    mma_bf16(s[nb2 * 2 + 1], afr, bfr[nb2][1], bfr[nb2][3]);
                }
            }
        }

        // ---- p = exp2(s) (log2e pre-folded), accumulate row sums ----
        float ps0 = 0.f, ps1 = 0.f;
        #pragma unroll
        for (int n = 0; n < 8; ++n) {
            s[n][0] = ex2(s[n][0]);
            s[n][1] = ex2(s[n][1]);
            s[n][2] = ex2(s[n][2]);
            s[n][3] = ex2(s[n][3]);
            ps0 += s[n][0] + s[n][1];
            ps1 += s[n][2] + s[n][3];
        }
        l0 += ps0;
        l1 += ps1;

        // ---- O += P @ V ----
        #pragma unroll
        for (int kk = 0; kk < 4; ++kk) {
            uint32_t a[4];
            a[0] = packbf(s[2 * kk][0],     s[2 * kk][1]);
            a[1] = packbf(s[2 * kk][2],     s[2 * kk][3]);
            a[2] = packbf(s[2 * kk + 1][0], s[2 * kk + 1][1]);
            a[3] = packbf(s[2 * kk + 1][2], s[2 * kk + 1][3]);
            const int key = kk * 16 + keyl;
            #pragma unroll
            for (int dg = 0; dg < 8; ++dg) {
                const int d0 = dg * 16 + dl8;
                uint32_t vfr[4];
                LDM4T(vfr, Vs + st + (uint32_t)(d0 >> 6) * 8192u +
                           swz((uint32_t)(key * 128 + (d0 & 63) * 2)));
                mma_bf16(acc_o[dg * 2],     a, vfr[0], vfr[1]);
                mma_bf16(acc_o[dg * 2 + 1], a, vfr[2], vfr[3]);
            }
        }
    }

    if (!big) {
        // ---- small: dump raw partials + release flag ----
        float* po = g_po + (size_t)tile * 32768 + (size_t)tid * 128;
        #pragma unroll
        for (int n = 0; n < 32; ++n)
            *(float4*)(po + n * 4) = make_float4(acc_o[n][0], acc_o[n][1],
                                                 acc_o[n][2], acc_o[n][3]);
        *(float2*)&g_pl[tile * 512 + tid * 2] = make_float2(l0, l1);
        __threadfence();
        __syncthreads();
        if (tid == 0) st_release(&g_flag[tile], 1);
        return;
    }

    __syncthreads();   // all warps done reading K/V smem of final iter

    // ---- stage Wp^T into dead K/V smem (overlaps with partner spin) ----
    #pragma unroll
    for (int l = 0; l < 32; ++l) {
        const int f  = tid + l * 256;
        const int nb = f >> 11;
        const int f2 = f & 2047;
        const int r = f2 >> 5, pan = (f2 >> 3) & 3, ch = f2 & 7;
        cp16(Wps + (uint32_t)nb * 32768u + (uint32_t)pan * 8192u +
                 swz((uint32_t)(r * 128 + ch * 16)),
             wpt + (size_t)(nb * 64 + r) * 256 + pan * 64 + ch * 8);
    }
    cp_commit();

    // ---- wait for partner, combine raw partials ----
    if (tid == 0) {
        while (ld_acquire(&g_flag[tile]) == 0) __nanosleep(64);
    }
    __syncthreads();
    {
        const float* po = g_po + (size_t)tile * 32768 + (size_t)tid * 128;
        #pragma unroll
        for (int n = 0; n < 32; ++n) {
            float4 v = *(const float4*)(po + n * 4);
            acc_o[n][0] += v.x; acc_o[n][1] += v.y;
            acc_o[n][2] += v.z; acc_o[n][3] += v.w;
        }
        float2 sl = *(const float2*)&g_pl[tile * 512 + tid * 2];
        l0 += sl.x;
        l1 += sl.y;
    }

    // ---- row-sum reduction ----
    l0 += __shfl_xor_sync(0xffffffffu, l0, 1);
    l0 += __shfl_xor_sync(0xffffffffu, l0, 2);
    l1 += __shfl_xor_sync(0xffffffffu, l1, 1);
    l1 += __shfl_xor_sync(0xffffffffu, l1, 2);
    const float i0 = 1.f / l0, i1 = 1.f / l1;

    // ---- normalized O A-fragments direct from registers (P-trick layout) ----
    uint32_t oa[16][4];
    #pragma unroll
    for (int kst = 0; kst < 16; ++kst) {
        oa[kst][0] = packbf(acc_o[2 * kst][0] * i0,     acc_o[2 * kst][1] * i0);
        oa[kst][1] = packbf(acc_o[2 * kst][2] * i1,     acc_o[2 * kst][3] * i1);
        oa[kst][2] = packbf(acc_o[2 * kst + 1][0] * i0, acc_o[2 * kst + 1][1] * i0);
        oa[kst][3] = packbf(acc_o[2 * kst + 1][2] * i1, acc_o[2 * kst + 1][3] * i1);
    }
    cp_wait0();
    __syncthreads();   // Wp^T visible to all

    // ---- proj GEMM: each warp owns rows wid*16..+15, loops 4 col-blocks ----
    const int lr = wid * 16 + (lane >> 2);
    const size_t gr = (size_t)b * NTOK + q0 + lr;

    #pragma unroll
    for (int nbq = 0; nbq < 4; ++nbq) {
        const uint32_t wb = Wps + (uint32_t)nbq * 32768u;
        float pa[8][4];
        #pragma unroll
        for (int j = 0; j < 8; j++)
            #pragma unroll
            for (int q = 0; q < 4; q++) pa[j][q] = 0.f;

        #pragma unroll
        for (int kst = 0; kst < 16; ++kst) {
            const uint32_t pan = (uint32_t)(kst >> 2);
            const uint32_t kby = (uint32_t)((kst & 3) * 32 + colb);
            uint32_t bfr[4][4];
            #pragma unroll
            for (int nb2 = 0; nb2 < 4; ++nb2)
                LDM4(bfr[nb2], wb + pan * 8192u +
                               swz((uint32_t)(l15 + nb2 * 16) * 128 + kby));
            #pragma unroll
            for (int nb2 = 0; nb2 < 4; ++nb2) {
                mma_bf16(pa[nb2 * 2],     oa[kst], bfr[nb2][0], bfr[nb2][2]);
                mma_bf16(pa[nb2 * 2 + 1], oa[kst], bfr[nb2][1], bfr[nb2][3]);
            }
        }

        // epilogue: bias + GroupNorm residual (stats from smem), fp32 out
        #pragma unroll
        for (int na = 0; na < 8; ++na) {
            const int cc = nbq * 64 + (na >> 1) * 16 + (na & 1) * 8 +
                           (lane & 3) * 2;
            const float2 st = sstat[cc >> 5];
            const float gm0 = gamma[cc], gm1 = gamma[cc + 1];
            const float bt0 = beta[cc],  bt1 = beta[cc + 1];
            const float b0 = bp[cc], b1 = bp[cc + 1];
            float2 xv0 = *(const float2*)&x[gr * 256 + cc];
            float2 xv1 = *(const float2*)&x[(gr + 8) * 256 + cc];
            float v0 = pa[na][0] + b0 + (xv0.x - st.x) * st.y * gm0 + bt0;
            float v1 = pa[na][1] + b1 + (xv0.y - st.x) * st.y * gm1 + bt1;
            float v2 = pa[na][2] + b0 + (xv1.x - st.x) * st.y * gm0 + bt0;
            float v3 = pa[na][3] + b1 + (xv1.y - st.x) * st.y * gm1 + bt1;
            *(float2*)(out + gr * 256 + cc)       = make_float2(v0, v1);
            *(float2*)(out + (gr + 8) * 256 + cc) = make_float2(v2, v3);
        }
    }
}

// ---------------- launch ------------------------------------------------------
extern "C" void kernel_launch(void* const* d_in, const int* in_sizes, int n_in,
                              void* d_out, int out_size)
{
    const float* x     = (const float*)d_in[0];
    const float* gamma = (const float*)d_in[1];
    const float* beta  = (const float*)d_in[2];
    const float* Wq    = (const float*)d_in[3];
    const float* bq    = (const float*)d_in[4];
    const float* Wk    = (const float*)d_in[5];
    const float* bk    = (const float*)d_in[6];
    const float* Wv    = (const float*)d_in[7];
    const float* bv    = (const float*)d_in[8];
    const float* Wp    = (const float*)d_in[9];
    const float* bp    = (const float*)d_in[10];
    float* out = (float*)d_out;

    float *b3, *part;  bf16 *qkv, *wt, *wpt;
    cudaGetSymbolAddress((void**)&qkv,  g_qkv);
    cudaGetSymbolAddress((void**)&wt,   g_wt);
    cudaGetSymbolAddress((void**)&wpt,  g_wpt);
    cudaGetSymbolAddress((void**)&b3,   g_b3);
    cudaGetSymbolAddress((void**)&part, g_part);

    cudaFuncSetAttribute(qkv_gemm,     cudaFuncAttributeMaxDynamicSharedMemorySize, QSM);
    cudaFuncSetAttribute(flash_kernel, cudaFuncAttributeMaxDynamicSharedMemorySize, FSM);

    // 1) weight prep + GN partial sums + split-K flag reset (merged)
    prep_gn_kernel<<<1280, 256>>>(Wq, Wk, Wv, Wp, wt, wpt, bq, bk, bv, b3,
                                  x, part);

    // 2) fused QKV with inline GroupNorm: GN(x) @ [768,256]^T + bias -> qkv
    qkv_gemm<<<dim3(6, 128), 256, QSM>>>(x, gamma, beta, part, wt, b3, qkv);

    // 3) key-split fused attention + projection + GN residual -> out (fp32)
    flash_kernel<<<256, 256, FSM>>>(qkv, wpt, bp, x, part, gamma, beta, out);
}

// round 14
// speedup vs baseline: 1.0383x; 1.0383x over previous
#include <cuda_runtime.h>
#include <cuda_bf16.h>
#include <cstdint>
#include <cstddef>

using bf16  = __nv_bfloat16;
using bf162 = __nv_bfloat162;

#define BATCH  4
#define NTOK   4096
#define CDIM   256
#define GROUPS 8
#define EPSV   1e-3f
#define GNM    131072.0f     // elements per (b,g) group

// q pre-scale: (1/16 softmax scale) * log2(e) so exp(x) == exp2(s)
#define QSCALE 0.09016843806266f

// ---------------- static device scratch (no cudaMalloc) ---------------------
__device__ bf16  g_qkv  [(size_t)BATCH * NTOK * 3 * CDIM];
__device__ bf16  g_wt   [3 * CDIM * CDIM];
__device__ bf16  g_wpt  [CDIM * CDIM];
__device__ float g_b3   [3 * CDIM];
__device__ float g_part [BATCH * GROUPS * 32 * 2];  // partial sums

// ---------------- helpers -----------------------------------------------------
__device__ __forceinline__ uint32_t smem_u32(const void* p) {
    uint32_t a;
    asm("{ .reg .u64 t; cvta.to.shared.u64 t, %1; cvt.u32.u64 %0, t; }"
        : "=r"(a) : "l"(p));
    return a;
}
__device__ __forceinline__ uint32_t swz(uint32_t b) { return b ^ ((b >> 3) & 0x70); }

#define LDM4(r, addr) \
    asm volatile("ldmatrix.sync.aligned.m8n8.x4.shared.b16 {%0,%1,%2,%3}, [%4];" \
        : "=r"((r)[0]), "=r"((r)[1]), "=r"((r)[2]), "=r"((r)[3]) : "r"(addr))
#define LDM4T(r, addr) \
    asm volatile("ldmatrix.sync.aligned.m8n8.x4.trans.shared.b16 {%0,%1,%2,%3}, [%4];" \
        : "=r"((r)[0]), "=r"((r)[1]), "=r"((r)[2]), "=r"((r)[3]) : "r"(addr))

__device__ __forceinline__ void mma_bf16(float* c, const uint32_t* a,
                                         uint32_t b0, uint32_t b1) {
    asm volatile(
        "mma.sync.aligned.m16n8k16.row.col.f32.bf16.bf16.f32 "
        "{%0,%1,%2,%3}, {%4,%5,%6,%7}, {%8,%9}, {%0,%1,%2,%3};"
        : "+f"(c[0]), "+f"(c[1]), "+f"(c[2]), "+f"(c[3])
        : "r"(a[0]), "r"(a[1]), "r"(a[2]), "r"(a[3]), "r"(b0), "r"(b1));
}

__device__ __forceinline__ void cp16(uint32_t saddr, const void* gaddr) {
    asm volatile("cp.async.cg.shared.global [%0], [%1], 16;"
                 :: "r"(saddr), "l"(gaddr));
}
__device__ __forceinline__ void cp_commit() {
    asm volatile("cp.async.commit_group;" ::: "memory");
}
__device__ __forceinline__ void cp_wait1() {
    asm volatile("cp.async.wait_group 1;" ::: "memory");
}
__device__ __forceinline__ void cp_wait0() {
    asm volatile("cp.async.wait_group 0;" ::: "memory");
}
__device__ __forceinline__ uint32_t packbf(float a, float b) {
    bf162 p = __floats2bfloat162_rn(a, b);
    return *(uint32_t*)&p;
}
__device__ __forceinline__ float ex2(float x) {
    float r;
    asm("ex2.approx.f32 %0, %1;" : "=f"(r) : "f"(x));
    return r;
}
__device__ __forceinline__ void sts64(uint32_t a, uint32_t v0, uint32_t v1) {
    asm volatile("st.shared.v2.b32 [%0], {%1,%2};" :: "r"(a), "r"(v0), "r"(v1));
}

// ---- per-CTA GroupNorm stats: 8 warps reduce 32 partials each -> sstat[8] ----
__device__ __forceinline__ void compute_stats(const float* __restrict__ part,
                                              int b, int wid, int lane,
                                              float2* sstat)
{
    const float2 p = *(const float2*)&part[(((b << 3) + wid) * 32 + lane) * 2];
    float s = p.x, ss = p.y;
    #pragma unroll
    for (int o = 16; o; o >>= 1) {
        s  += __shfl_xor_sync(0xffffffffu, s,  o);
        ss += __shfl_xor_sync(0xffffffffu, ss, o);
    }
    if (lane == 0) {
        const float mean = s / GNM;
        sstat[wid] = make_float2(mean, rsqrtf(ss / GNM - mean * mean + EPSV));
    }
}

// ---------------- merged: weight prep (256 blocks) + GN partial (1024) -------
__global__ void __launch_bounds__(256)
prep_gn_kernel(const float* __restrict__ Wq, const float* __restrict__ Wk,
               const float* __restrict__ Wv, const float* __restrict__ Wp,
               bf16* __restrict__ wt, bf16* __restrict__ wpt,
               const float* __restrict__ bq, const float* __restrict__ bk,
               const float* __restrict__ bv, float* __restrict__ b3,
               const float* __restrict__ x, float* __restrict__ part)
{
    const int tid = threadIdx.x;
    if (blockIdx.x < 1024) {
        // ---- GN partial sums (front-batched loads, 4 indep accumulators) ----
        const int bg = blockIdx.x >> 5, slab = blockIdx.x & 31;
        const int b = bg >> 3, g = bg & 7;
        const size_t base = (size_t)b * NTOK * CDIM + (size_t)g * 32 +
                            (size_t)(slab * 128) * CDIM;

        float4 v[4];
        #pragma unroll
        for (int u = 0; u < 4; ++u) {
            const int i = tid + u * 256;
            const int m = i >> 3, qd = i & 7;
            v[u] = *(const float4*)&x[base + (size_t)m * CDIM + qd * 4];
        }
        float s0 = 0.f, s1 = 0.f, s2 = 0.f, s3 = 0.f;
        float q0 = 0.f, q1 = 0.f, q2 = 0.f, q3 = 0.f;
        s0 = v[0].x + v[0].y + v[0].z + v[0].w;
        s1 = v[1].x + v[1].y + v[1].z + v[1].w;
        s2 = v[2].x + v[2].y + v[2].z + v[2].w;
        s3 = v[3].x + v[3].y + v[3].z + v[3].w;
        q0 = v[0].x * v[0].x + v[0].y * v[0].y + v[0].z * v[0].z + v[0].w * v[0].w;
        q1 = v[1].x * v[1].x + v[1].y * v[1].y + v[1].z * v[1].z + v[1].w * v[1].w;
        q2 = v[2].x * v[2].x + v[2].y * v[2].y + v[2].z * v[2].z + v[2].w * v[2].w;
        q3 = v[3].x * v[3].x + v[3].y * v[3].y + v[3].z * v[3].z + v[3].w * v[3].w;
        float s  = (s0 + s1) + (s2 + s3);
        float ss = (q0 + q1) + (q2 + q3);

        #pragma unroll
        for (int o = 16; o; o >>= 1) {
            s  += __shfl_xor_sync(0xffffffffu, s,  o);
            ss += __shfl_xor_sync(0xffffffffu, ss, o);
        }
        __shared__ float shs[8], shss[8];
        if (!(tid & 31)) { shs[tid >> 5] = s; shss[tid >> 5] = ss; }
        __syncthreads();
        if (tid == 0) {
            float st = 0.f, sst = 0.f;
            #pragma unroll
            for (int i = 0; i < 8; i++) { st += shs[i]; sst += shss[i]; }
            part[blockIdx.x * 2]     = st;
            part[blockIdx.x * 2 + 1] = sst;
        }
    } else {
        // ---- weight transpose + convert ----
        const int idx = blockIdx.x - 1024;
        const int z = idx >> 6;
        const int bxq = (idx & 7) * 32, byq = ((idx >> 3) & 7) * 32;
        const float* W = (z == 0) ? Wq : (z == 1) ? Wk : (z == 2) ? Wv : Wp;
        bf16* out = (z < 3) ? (wt + (size_t)z * CDIM * CDIM) : wpt;
        const float scale = (z == 0) ? QSCALE : 1.0f;

        __shared__ float t[32][33];
        const int tx = tid & 31, ty = tid >> 5;
        for (int yy = ty; yy < 32; yy += 8)
            t[yy][tx] = W[(size_t)(byq + yy) * CDIM + bxq + tx];
        __syncthreads();
        for (int yy = ty; yy < 32; yy += 8)
            out[(size_t)(bxq + yy) * CDIM + byq + tx] =
                __float2bfloat16(t[tx][yy] * scale);

        if (z == 3 && idx == 192) {   // z==3, x==0, y==0
            for (int j = tid; j < 768; j += 256)
                b3[j] = (j < 256) ? bq[j] * QSCALE
                      : (j < 512) ? bk[j - 256] : bv[j - 512];
        }
    }
}

// ---------------- QKV GEMM with inline GroupNorm on A (R10 proven shape) -----
#define QSM (1024 + 65536 + 32768)

__device__ __forceinline__ void cpb_tile(uint32_t sdst,
    const bf16* __restrict__ g, int row0, int k0, int tid)
{
    #pragma unroll
    for (int l = 0; l < 4; ++l) {
        const int f = tid + l * 256;
        const int r = f >> 3;
        const int q = f & 7;
        cp16(sdst + swz((uint32_t)(r * 128 + q * 16)),
             g + (size_t)(row0 + r) * 256 + k0 + q * 8);
    }
}

__global__ void __launch_bounds__(256)
qkv_gemm(const float* __restrict__ x, const float* __restrict__ gamma,
         const float* __restrict__ beta, const float* __restrict__ part,
         const bf16* __restrict__ wt, const float* __restrict__ b3,
         bf16* __restrict__ C)
{
    extern __shared__ char smraw[];
    const uint32_t base = (smem_u32(smraw) + 1023u) & ~1023u;
    const uint32_t As = base;              // 64KB: 4 panels of 128x64 cols
    const uint32_t Bs = base + 65536u;     // 2x16KB B double buffer
    __shared__ float2 sstat[8];

    const int tid  = threadIdx.x;
    const int wid  = tid >> 5;
    const int lane = tid & 31;
    const int wm   = wid & 3;
    const int wn   = wid >> 2;
    const int row0 = blockIdx.y * 128;
    const int b    = row0 >> 12;
    const int col0 = blockIdx.x * 128;

    compute_stats(part, b, wid, lane, sstat);
    cpb_tile(Bs, wt, col0, 0, tid);
    cp_commit();
    __syncthreads();   // sstat visible

    // A: load x fp32, normalize, pack bf16, store to panel-format smem
    #pragma unroll
    for (int l = 0; l < 32; ++l) {
        const int f  = tid + l * 256;
        const int r  = f >> 6;
        const int c4 = f & 63;
        float4 xv = *(const float4*)&x[(size_t)(row0 + r) * 256 + c4 * 4];
        float4 gm = *(const float4*)&gamma[c4 * 4];
        float4 bt = *(const float4*)&beta [c4 * 4];
        const float2 st = sstat[c4 >> 3];
        const uint32_t u0 = packbf((xv.x - st.x) * st.y * gm.x + bt.x,
                                   (xv.y - st.x) * st.y * gm.y + bt.y);
        const uint32_t u1 = packbf((xv.z - st.x) * st.y * gm.z + bt.z,
                                   (xv.w - st.x) * st.y * gm.w + bt.w);
        sts64(As + (uint32_t)(c4 >> 4) * 16384u +
                  swz((uint32_t)(r * 128 + (c4 & 15) * 8)), u0, u1);
    }

    const int arow  = wm * 32 + (lane & 15);
    const int brow  = wn * 64 + (lane & 15);
    const int colb  = (lane >> 4) * 16;

    float acc[2][8][4];
    #pragma unroll
    for (int i = 0; i < 2; i++)
        #pragma unroll
        for (int j = 0; j < 8; j++)
            #pragma unroll
            for (int q = 0; q < 4; q++) acc[i][j][q] = 0.f;

    for (int i = 0; i < 4; ++i) {
        if (i + 1 < 4) {
            cpb_tile(Bs + (uint32_t)((i + 1) & 1) * 16384u,
                     wt, col0, (i + 1) * 64, tid);
            cp_commit();
            cp_wait1();
        } else {
            cp_wait0();
        }
        __syncthreads();

        const uint32_t ap = As + (uint32_t)i * 16384u;
        const uint32_t bb = Bs + (uint32_t)(i & 1) * 16384u;
        #pragma unroll
        for (int kst = 0; kst < 4; ++kst) {
            const uint32_t kb = (uint32_t)(kst * 32 + colb);
            uint32_t afr[2][4], bfr[4][4];
            LDM4(afr[0], ap + swz((uint32_t)(arow)      * 128 + kb));
            LDM4(afr[1], ap + swz((uint32_t)(arow + 16) * 128 + kb));
            #pragma unroll
            for (int nb2 = 0; nb2 < 4; ++nb2)
                LDM4(bfr[nb2], bb + swz((uint32_t)(brow + nb2 * 16) * 128 + kb));
            #pragma unroll
            for (int ma = 0; ma < 2; ++ma)
                #pragma unroll
                for (int nb2 = 0; nb2 < 4; ++nb2) {
                    mma_bf16(acc[ma][nb2 * 2],     afr[ma], bfr[nb2][0], bfr[nb2][2]);
                    mma_bf16(acc[ma][nb2 * 2 + 1], afr[ma], bfr[nb2][1], bfr[nb2][3]);
                }
        }
        __syncthreads();
    }

    #pragma unroll
    for (int ma = 0; ma < 2; ++ma) {
        const size_t r0 = (size_t)(row0 + wm * 32 + ma * 16 + (lane >> 2));
        #pragma unroll
        for (int na = 0; na < 8; ++na) {
            const int cc = col0 + wn * 64 + (na >> 1) * 16 + (na & 1) * 8 +
                           (lane & 3) * 2;
            const float b0 = b3[cc], b1 = b3[cc + 1];
            *(uint32_t*)(C + r0 * 768 + cc) =
                packbf(acc[ma][na][0] + b0, acc[ma][na][1] + b1);
            *(uint32_t*)(C + (r0 + 8) * 768 + cc) =
                packbf(acc[ma][na][2] + b0, acc[ma][na][3] + b1);
        }
    }
}

// ---------------- fused flash attention + output projection (R10 proven) -----
#define FSM (1024 + 196608)

__global__ void __launch_bounds__(256, 1)
flash_kernel(const bf16* __restrict__ qkv, const bf16* __restrict__ wpt,
             const float* __restrict__ bp, const float* __restrict__ x,
             const float* __restrict__ part, const float* __restrict__ gamma,
             const float* __restrict__ beta, float* __restrict__ out)
{
    extern __shared__ char smraw[];
    const uint32_t base = (smem_u32(smraw) + 1023u) & ~1023u;
    const uint32_t Qs  = base;                 // 64KB Q
    const uint32_t Ks  = base + 65536u;        // 64KB K 2 stages
    const uint32_t Vs  = base + 131072u;       // 64KB V 2 stages
    const uint32_t Wps = base + 65536u;        // epilogue: Wp^T 128KB over K+V
    __shared__ float2 sstat[8];

    const int tid  = threadIdx.x;
    const int wid  = tid >> 5;
    const int lane = tid & 31;
    const int q0   = blockIdx.x * 128;
    const int b    = blockIdx.y;
    const bf16* qp = qkv + (size_t)b * NTOK * 768;
    const bf16* kp = qp + 256;
    const bf16* vp = qp + 512;

    #pragma unroll
    for (int l = 0; l < 16; ++l) {
        const int f = tid + l * 256;
        const int r = f >> 5, pan = (f >> 3) & 3, ch = f & 7;
        cp16(Qs + pan * 16384u + swz((uint32_t)(r * 128 + ch * 16)),
             qp + (size_t)(q0 + r) * 768 + pan * 64 + ch * 8);
    }
    #pragma unroll
    for (int l = 0; l < 8; ++l) {
        const int f = tid + l * 256;
        const int r = f >> 5, pan = (f >> 3) & 3, ch = f & 7;
        const uint32_t so = (uint32_t)pan * 8192u + swz((uint32_t)(r * 128 + ch * 16));
        cp16(Ks + so, kp + (size_t)r * 768 + pan * 64 + ch * 8);
        cp16(Vs + so, vp + (size_t)r * 768 + pan * 64 + ch * 8);
    }
    cp_commit();

    // GN stats for epilogue residual (overlapped with prologue loads)
    compute_stats(part, b, wid, lane, sstat);

    const int l15  = lane & 15;
    const int arow = wid * 16 + l15;
    const int colb = (lane >> 4) * 16;
    const int keyl = ((lane >> 3) & 1) * 8 + (lane & 7);
    const int dl8  = (lane >> 4) * 8;

    float acc_o[32][4];
    #pragma unroll
    for (int n = 0; n < 32; ++n)
        #pragma unroll
        for (int q = 0; q < 4; ++q) acc_o[n][q] = 0.f;
    float l0 = 0.f, l1 = 0.f;

    const int NBLK = NTOK / 64;
    for (int j = 0; j < NBLK; ++j) {
        const uint32_t st = (uint32_t)(j & 1) * 32768u;

        __syncthreads();   // stage (j+1)&1 fully consumed (iter j-1)
        if (j + 1 < NBLK) {
            const uint32_t stn = (uint32_t)((j + 1) & 1) * 32768u;
            const int key0 = (j + 1) * 64;
            #pragma unroll
            for (int l = 0; l < 8; ++l) {
                const int f = tid + l * 256;
                const int r = f >> 5, pan = (f >> 3) & 3, ch = f & 7;
                const uint32_t so = (uint32_t)pan * 8192u +
                                    swz((uint32_t)(r * 128 + ch * 16));
                cp16(Ks + stn + so, kp + (size_t)(key0 + r) * 768 + pan * 64 + ch * 8);
                cp16(Vs + stn + so, vp + (size_t)(key0 + r) * 768 + pan * 64 + ch * 8);
            }
            cp_commit();
            cp_wait1();
        } else {
            cp_wait0();
        }

        // ---- S = Q @ K^T ----
        float s[8][4];
        #pragma unroll
        for (int n = 0; n < 8; ++n)
            #pragma unroll
            for (int q = 0; q < 4; ++q) s[n][q] = 0.f;

        #pragma unroll
        for (int pan = 0; pan < 4; ++pan) {
            const uint32_t qb = Qs + (uint32_t)pan * 16384u;
            const uint32_t kb = Ks + st + (uint32_t)pan * 8192u;
            #pragma unroll
            for (int kst = 0; kst < 4; ++kst) {
                const uint32_t kby = (uint32_t)(kst * 32 + colb);
                uint32_t afr[4], bfr[4][4];
                LDM4(afr, qb + swz((uint32_t)arow * 128 + kby));
                #pragma unroll
                for (int nb2 = 0; nb2 < 4; ++nb2)
                    LDM4(bfr[nb2], kb + swz((uint32_t)(l15 + nb2 * 16) * 128 + kby));
                #pragma unroll
                for (int nb2 = 0; nb2 < 4; ++nb2) {
                    mma_bf16(s[nb2 * 2],     afr, bfr[nb2][0], bfr[nb2][2]);
                    mma_bf16(s[nb2 * 2 + 1], afr, bfr[nb2][1], bfr[nb2][3]);
                }
            }
        }

        // ---- p = exp2(s) (log2e pre-folded), accumulate row sums ----
        float ps0 = 0.f, ps1 = 0.f;
        #pragma unroll
        for (int n = 0; n < 8; ++n) {
            s[n][0] = ex2(s[n][0]);
            s[n][1] = ex2(s[n][1]);
            s[n][2] = ex2(s[n][2]);
            s[n][3] = ex2(s[n][3]);
            ps0 += s[n][0] + s[n][1];
            ps1 += s[n][2] + s[n][3];
        }
        l0 += ps0;
        l1 += ps1;

        // ---- O += P @ V ----
        #pragma unroll
        for (int kk = 0; kk < 4; ++kk) {
            uint32_t a[4];
            a[0] = packbf(s[2 * kk][0],     s[2 * kk][1]);
            a[1] = packbf(s[2 * kk][2],     s[2 * kk][3]);
            a[2] = packbf(s[2 * kk + 1][0], s[2 * kk + 1][1]);
            a[3] = packbf(s[2 * kk + 1][2], s[2 * kk + 1][3]);
            const int key = kk * 16 + keyl;
            #pragma unroll
            for (int dg = 0; dg < 8; ++dg) {
                const int d0 = dg * 16 + dl8;
                uint32_t vfr[4];
                LDM4T(vfr, Vs + st + (uint32_t)(d0 >> 6) * 8192u +
                           swz((uint32_t)(key * 128 + (d0 & 63) * 2)));
                mma_bf16(acc_o[dg * 2],     a, vfr[0], vfr[1]);
                mma_bf16(acc_o[dg * 2 + 1], a, vfr[2], vfr[3]);
            }
        }
    }

    // ---- row-sum reduction ----
    l0 += __shfl_xor_sync(0xffffffffu, l0, 1);
    l0 += __shfl_xor_sync(0xffffffffu, l0, 2);
    l1 += __shfl_xor_sync(0xffffffffu, l1, 1);
    l1 += __shfl_xor_sync(0xffffffffu, l1, 2);
    const float i0 = 1.f / l0, i1 = 1.f / l1;

    __syncthreads();   // all warps done reading K/V smem of final iter

    // ---- stage Wp^T into dead K/V smem as 4 K-format 64x256 tiles ----
    #pragma unroll
    for (int l = 0; l < 32; ++l) {
        const int f  = tid + l * 256;     // 0..8191 16B chunks
        const int nb = f >> 11;           // 64-row block 0..3
        const int f2 = f & 2047;
        const int r = f2 >> 5, pan = (f2 >> 3) & 3, ch = f2 & 7;
        cp16(Wps + (uint32_t)nb * 32768u + (uint32_t)pan * 8192u +
                 swz((uint32_t)(r * 128 + ch * 16)),
             wpt + (size_t)(nb * 64 + r) * 256 + pan * 64 + ch * 8);
    }
    cp_commit();

    // ---- normalized O A-fragments direct from registers (P-trick layout) ----
    uint32_t oa[16][4];
    #pragma unroll
    for (int kst = 0; kst < 16; ++kst) {
        oa[kst][0] = packbf(acc_o[2 * kst][0] * i0,     acc_o[2 * kst][1] * i0);
        oa[kst][1] = packbf(acc_o[2 * kst][2] * i1,     acc_o[2 * kst][3] * i1);
        oa[kst][2] = packbf(acc_o[2 * kst + 1][0] * i0, acc_o[2 * kst + 1][1] * i0);
        oa[kst][3] = packbf(acc_o[2 * kst + 1][2] * i1, acc_o[2 * kst + 1][3] * i1);
    }
    cp_wait0();
    __syncthreads();   // Wp^T visible to all

    // ---- proj GEMM: each warp owns rows wid*16..+15, loops 4 col-blocks ----
    const int lr = wid * 16 + (lane >> 2);
    const size_t gr = (size_t)b * NTOK + q0 + lr;

    #pragma unroll
    for (int nbq = 0; nbq < 4; ++nbq) {
        const uint32_t wb = Wps + (uint32_t)nbq * 32768u;
        float pa[8][4];
        #pragma unroll
        for (int j = 0; j < 8; j++)
            #pragma unroll
            for (int q = 0; q < 4; q++) pa[j][q] = 0.f;

        #pragma unroll
        for (int kst = 0; kst < 16; ++kst) {
            const uint32_t pan = (uint32_t)(kst >> 2);
            const uint32_t kby = (uint32_t)((kst & 3) * 32 + colb);
            uint32_t bfr[4][4];
            #pragma unroll
            for (int nb2 = 0; nb2 < 4; ++nb2)
                LDM4(bfr[nb2], wb + pan * 8192u +
                               swz((uint32_t)(l15 + nb2 * 16) * 128 + kby));
            #pragma unroll
            for (int nb2 = 0; nb2 < 4; ++nb2) {
                mma_bf16(pa[nb2 * 2],     oa[kst], bfr[nb2][0], bfr[nb2][2]);
                mma_bf16(pa[nb2 * 2 + 1], oa[kst], bfr[nb2][1], bfr[nb2][3]);
            }
        }

        // epilogue: bias + GroupNorm residual (stats from smem), fp32 out
        #pragma unroll
        for (int na = 0; na < 8; ++na) {
            const int cc = nbq * 64 + (na >> 1) * 16 + (na & 1) * 8 +
                           (lane & 3) * 2;
            const float2 st = sstat[cc >> 5];
            const float gm0 = gamma[cc], gm1 = gamma[cc + 1];
            const float bt0 = beta[cc],  bt1 = beta[cc + 1];
            const float b0 = bp[cc], b1 = bp[cc + 1];
            float2 xv0 = *(const float2*)&x[gr * 256 + cc];
            float2 xv1 = *(const float2*)&x[(gr + 8) * 256 + cc];
            float v0 = pa[na][0] + b0 + (xv0.x - st.x) * st.y * gm0 + bt0;
            float v1 = pa[na][1] + b1 + (xv0.y - st.x) * st.y * gm1 + bt1;
            float v2 = pa[na][2] + b0 + (xv1.x - st.x) * st.y * gm0 + bt0;
            float v3 = pa[na][3] + b1 + (xv1.y - st.x) * st.y * gm1 + bt1;
            *(float2*)(out + gr * 256 + cc)       = make_float2(v0, v1);
            *(float2*)(out + (gr + 8) * 256 + cc) = make_float2(v2, v3);
        }
    }
}

// ---------------- launch ------------------------------------------------------
extern "C" void kernel_launch(void* const* d_in, const int* in_sizes, int n_in,
                              void* d_out, int out_size)
{
    const float* x     = (const float*)d_in[0];
    const float* gamma = (const float*)d_in[1];
    const float* beta  = (const float*)d_in[2];
    const float* Wq    = (const float*)d_in[3];
    const float* bq    = (const float*)d_in[4];
    const float* Wk    = (const float*)d_in[5];
    const float* bk    = (const float*)d_in[6];
    const float* Wv    = (const float*)d_in[7];
    const float* bv    = (const float*)d_in[8];
    const float* Wp    = (const float*)d_in[9];
    const float* bp    = (const float*)d_in[10];
    float* out = (float*)d_out;

    float *b3, *part;  bf16 *qkv, *wt, *wpt;
    cudaGetSymbolAddress((void**)&qkv,  g_qkv);
    cudaGetSymbolAddress((void**)&wt,   g_wt);
    cudaGetSymbolAddress((void**)&wpt,  g_wpt);
    cudaGetSymbolAddress((void**)&b3,   g_b3);
    cudaGetSymbolAddress((void**)&part, g_part);

    cudaFuncSetAttribute(qkv_gemm,     cudaFuncAttributeMaxDynamicSharedMemorySize, QSM);
    cudaFuncSetAttribute(flash_kernel, cudaFuncAttributeMaxDynamicSharedMemorySize, FSM);

    // 1) weight prep + GN partial sums (merged)
    prep_gn_kernel<<<1280, 256>>>(Wq, Wk, Wv, Wp, wt, wpt, bq, bk, bv, b3,
                                  x, part);

    // 2) fused QKV with inline GroupNorm: GN(x) @ [768,256]^T + bias -> qkv
    qkv_gemm<<<dim3(6, 128), 256, QSM>>>(x, gamma, beta, part, wt, b3, qkv);

    // 3) fused attention + projection + GN residual -> out (fp32)
    flash_kernel<<<dim3(NTOK / 128, BATCH), 256, FSM>>>(
        qkv, wpt, bp, x, part, gamma, beta, out);
}

// round 15
// speedup vs baseline: 1.0389x; 1.0006x over previous
#include <cuda_runtime.h>
#include <cuda_bf16.h>
#include <cstdint>
#include <cstddef>

using bf16  = __nv_bfloat16;
using bf162 = __nv_bfloat162;

#define BATCH  4
#define NTOK   4096
#define CDIM   256
#define GROUPS 8
#define EPSV   1e-3f
#define GNM    131072.0f     // elements per (b,g) group

// q pre-scale: (1/16 softmax scale) * log2(e) so exp(x) == exp2(s)
#define QSCALE 0.09016843806266f

// ---------------- static device scratch (no cudaMalloc) ---------------------
__device__ bf16  g_qkv  [(size_t)BATCH * NTOK * 3 * CDIM];
__device__ bf16  g_wt   [3 * CDIM * CDIM];
__device__ bf16  g_wpt  [CDIM * CDIM];
__device__ float g_b3   [3 * CDIM];
__device__ float g_part [BATCH * GROUPS * 32 * 2];  // partial sums

// ---------------- helpers -----------------------------------------------------
__device__ __forceinline__ uint32_t smem_u32(const void* p) {
    uint32_t a;
    asm("{ .reg .u64 t; cvta.to.shared.u64 t, %1; cvt.u32.u64 %0, t; }"
        : "=r"(a) : "l"(p));
    return a;
}
__device__ __forceinline__ uint32_t swz(uint32_t b) { return b ^ ((b >> 3) & 0x70); }

#define LDM4(r, addr) \
    asm volatile("ldmatrix.sync.aligned.m8n8.x4.shared.b16 {%0,%1,%2,%3}, [%4];" \
        : "=r"((r)[0]), "=r"((r)[1]), "=r"((r)[2]), "=r"((r)[3]) : "r"(addr))
#define LDM4T(r, addr) \
    asm volatile("ldmatrix.sync.aligned.m8n8.x4.trans.shared.b16 {%0,%1,%2,%3}, [%4];" \
        : "=r"((r)[0]), "=r"((r)[1]), "=r"((r)[2]), "=r"((r)[3]) : "r"(addr))

__device__ __forceinline__ void mma_bf16(float* c, const uint32_t* a,
                                         uint32_t b0, uint32_t b1) {
    asm volatile(
        "mma.sync.aligned.m16n8k16.row.col.f32.bf16.bf16.f32 "
        "{%0,%1,%2,%3}, {%4,%5,%6,%7}, {%8,%9}, {%0,%1,%2,%3};"
        : "+f"(c[0]), "+f"(c[1]), "+f"(c[2]), "+f"(c[3])
        : "r"(a[0]), "r"(a[1]), "r"(a[2]), "r"(a[3]), "r"(b0), "r"(b1));
}

__device__ __forceinline__ void cp16(uint32_t saddr, const void* gaddr) {
    asm volatile("cp.async.cg.shared.global [%0], [%1], 16;"
                 :: "r"(saddr), "l"(gaddr));
}
__device__ __forceinline__ void cp_commit() {
    asm volatile("cp.async.commit_group;" ::: "memory");
}
__device__ __forceinline__ void cp_wait1() {
    asm volatile("cp.async.wait_group 1;" ::: "memory");
}
__device__ __forceinline__ void cp_wait0() {
    asm volatile("cp.async.wait_group 0;" ::: "memory");
}
__device__ __forceinline__ uint32_t packbf(float a, float b) {
    bf162 p = __floats2bfloat162_rn(a, b);
    return *(uint32_t*)&p;
}
__device__ __forceinline__ float ex2(float x) {
    float r;
    asm("ex2.approx.f32 %0, %1;" : "=f"(r) : "f"(x));
    return r;
}
__device__ __forceinline__ void sts64(uint32_t a, uint32_t v0, uint32_t v1) {
    asm volatile("st.shared.v2.b32 [%0], {%1,%2};" :: "r"(a), "r"(v0), "r"(v1));
}

// ---- per-CTA GroupNorm stats: 8 warps reduce 32 partials each -> sstat[8] ----
__device__ __forceinline__ void compute_stats(const float* __restrict__ part,
                                              int b, int wid, int lane,
                                              float2* sstat)
{
    const float2 p = *(const float2*)&part[(((b << 3) + wid) * 32 + lane) * 2];
    float s = p.x, ss = p.y;
    #pragma unroll
    for (int o = 16; o; o >>= 1) {
        s  += __shfl_xor_sync(0xffffffffu, s,  o);
        ss += __shfl_xor_sync(0xffffffffu, ss, o);
    }
    if (lane == 0) {
        const float mean = s / GNM;
        sstat[wid] = make_float2(mean, rsqrtf(ss / GNM - mean * mean + EPSV));
    }
}

// ---------------- merged: weight prep (256 blocks) + GN partial (1024) -------
__global__ void __launch_bounds__(256)
prep_gn_kernel(const float* __restrict__ Wq, const float* __restrict__ Wk,
               const float* __restrict__ Wv, const float* __restrict__ Wp,
               bf16* __restrict__ wt, bf16* __restrict__ wpt,
               const float* __restrict__ bq, const float* __restrict__ bk,
               const float* __restrict__ bv, float* __restrict__ b3,
               const float* __restrict__ x, float* __restrict__ part)
{
    const int tid = threadIdx.x;
    if (blockIdx.x < 1024) {
        // ---- GN partial sums ----
        const int bg = blockIdx.x >> 5, slab = blockIdx.x & 31;
        const int b = bg >> 3, g = bg & 7;
        const size_t base = (size_t)b * NTOK * CDIM + (size_t)g * 32 +
                            (size_t)(slab * 128) * CDIM;

        float s = 0.f, ss = 0.f;
        #pragma unroll
        for (int i = tid; i < 128 * 8; i += 256) {
            const int m = i >> 3, qd = i & 7;
            float4 v = *(const float4*)&x[base + (size_t)m * CDIM + qd * 4];
            s  += v.x + v.y + v.z + v.w;
            ss += v.x * v.x + v.y * v.y + v.z * v.z + v.w * v.w;
        }
        #pragma unroll
        for (int o = 16; o; o >>= 1) {
            s  += __shfl_xor_sync(0xffffffffu, s,  o);
            ss += __shfl_xor_sync(0xffffffffu, ss, o);
        }
        __shared__ float shs[8], shss[8];
        if (!(tid & 31)) { shs[tid >> 5] = s; shss[tid >> 5] = ss; }
        __syncthreads();
        if (tid == 0) {
            float st = 0.f, sst = 0.f;
            #pragma unroll
            for (int i = 0; i < 8; i++) { st += shs[i]; sst += shss[i]; }
            part[blockIdx.x * 2]     = st;
            part[blockIdx.x * 2 + 1] = sst;
        }
    } else {
        // ---- weight transpose + convert ----
        const int idx = blockIdx.x - 1024;
        const int z = idx >> 6;
        const int bxq = (idx & 7) * 32, byq = ((idx >> 3) & 7) * 32;
        const float* W = (z == 0) ? Wq : (z == 1) ? Wk : (z == 2) ? Wv : Wp;
        bf16* out = (z < 3) ? (wt + (size_t)z * CDIM * CDIM) : wpt;
        const float scale = (z == 0) ? QSCALE : 1.0f;

        __shared__ float t[32][33];
        const int tx = tid & 31, ty = tid >> 5;
        for (int yy = ty; yy < 32; yy += 8)
            t[yy][tx] = W[(size_t)(byq + yy) * CDIM + bxq + tx];
        __syncthreads();
        for (int yy = ty; yy < 32; yy += 8)
            out[(size_t)(bxq + yy) * CDIM + byq + tx] =
                __float2bfloat16(t[tx][yy] * scale);

        if (z == 3 && idx == 192) {   // z==3, x==0, y==0
            for (int j = tid; j < 768; j += 256)
                b3[j] = (j < 256) ? bq[j] * QSCALE
                      : (j < 512) ? bk[j - 256] : bv[j - 512];
        }
    }
}

// ---------------- QKV GEMM with inline GroupNorm on A (per-batch grid) -------
#define QSM (1024 + 65536 + 32768)

__device__ __forceinline__ void cpb_tile(uint32_t sdst,
    const bf16* __restrict__ g, int row0, int k0, int tid)
{
    #pragma unroll
    for (int l = 0; l < 4; ++l) {
        const int f = tid + l * 256;
        const int r = f >> 3;
        const int q = f & 7;
        cp16(sdst + swz((uint32_t)(r * 128 + q * 16)),
             g + (size_t)(row0 + r) * 256 + k0 + q * 8);
    }
}

__global__ void __launch_bounds__(256)
qkv_gemm(const float* __restrict__ x, const float* __restrict__ gamma,
         const float* __restrict__ beta, const float* __restrict__ part,
         const bf16* __restrict__ wt, const float* __restrict__ b3,
         bf16* __restrict__ C, int batch)
{
    extern __shared__ char smraw[];
    const uint32_t base = (smem_u32(smraw) + 1023u) & ~1023u;
    const uint32_t As = base;              // 64KB: 4 panels of 128x64 cols
    const uint32_t Bs = base + 65536u;     // 2x16KB B double buffer
    __shared__ float2 sstat[8];

    const int tid  = threadIdx.x;
    const int wid  = tid >> 5;
    const int lane = tid & 31;
    const int wm   = wid & 3;
    const int wn   = wid >> 2;
    const int row0 = batch * NTOK + blockIdx.y * 128;
    const int b    = batch;
    const int col0 = blockIdx.x * 128;

    compute_stats(part, b, wid, lane, sstat);
    cpb_tile(Bs, wt, col0, 0, tid);
    cp_commit();
    __syncthreads();   // sstat visible

    // A: load x fp32, normalize, pack bf16, store to panel-format smem
    #pragma unroll
    for (int l = 0; l < 32; ++l) {
        const int f  = tid + l * 256;
        const int r  = f >> 6;
        const int c4 = f & 63;
        float4 xv = *(const float4*)&x[(size_t)(row0 + r) * 256 + c4 * 4];
        float4 gm = *(const float4*)&gamma[c4 * 4];
        float4 bt = *(const float4*)&beta [c4 * 4];
        const float2 st = sstat[c4 >> 3];
        const uint32_t u0 = packbf((xv.x - st.x) * st.y * gm.x + bt.x,
                                   (xv.y - st.x) * st.y * gm.y + bt.y);
        const uint32_t u1 = packbf((xv.z - st.x) * st.y * gm.z + bt.z,
                                   (xv.w - st.x) * st.y * gm.w + bt.w);
        sts64(As + (uint32_t)(c4 >> 4) * 16384u +
                  swz((uint32_t)(r * 128 + (c4 & 15) * 8)), u0, u1);
    }

    const int arow  = wm * 32 + (lane & 15);
    const int brow  = wn * 64 + (lane & 15);
    const int colb  = (lane >> 4) * 16;

    float acc[2][8][4];
    #pragma unroll
    for (int i = 0; i < 2; i++)
        #pragma unroll
        for (int j = 0; j < 8; j++)
            #pragma unroll
            for (int q = 0; q < 4; q++) acc[i][j][q] = 0.f;

    for (int i = 0; i < 4; ++i) {
        if (i + 1 < 4) {
            cpb_tile(Bs + (uint32_t)((i + 1) & 1) * 16384u,
                     wt, col0, (i + 1) * 64, tid);
            cp_commit();
            cp_wait1();
        } else {
            cp_wait0();
        }
        __syncthreads();

        const uint32_t ap = As + (uint32_t)i * 16384u;
        const uint32_t bb = Bs + (uint32_t)(i & 1) * 16384u;
        #pragma unroll
        for (int kst = 0; kst < 4; ++kst) {
            const uint32_t kb = (uint32_t)(kst * 32 + colb);
            uint32_t afr[2][4], bfr[4][4];
            LDM4(afr[0], ap + swz((uint32_t)(arow)      * 128 + kb));
            LDM4(afr[1], ap + swz((uint32_t)(arow + 16) * 128 + kb));
            #pragma unroll
            for (int nb2 = 0; nb2 < 4; ++nb2)
                LDM4(bfr[nb2], bb + swz((uint32_t)(brow + nb2 * 16) * 128 + kb));
            #pragma unroll
            for (int ma = 0; ma < 2; ++ma)
                #pragma unroll
                for (int nb2 = 0; nb2 < 4; ++nb2) {
                    mma_bf16(acc[ma][nb2 * 2],     afr[ma], bfr[nb2][0], bfr[nb2][2]);
                    mma_bf16(acc[ma][nb2 * 2 + 1], afr[ma], bfr[nb2][1], bfr[nb2][3]);
                }
        }
        __syncthreads();
    }

    #pragma unroll
    for (int ma = 0; ma < 2; ++ma) {
        const size_t r0 = (size_t)(row0 + wm * 32 + ma * 16 + (lane >> 2));
        #pragma unroll
        for (int na = 0; na < 8; ++na) {
            const int cc = col0 + wn * 64 + (na >> 1) * 16 + (na & 1) * 8 +
                           (lane & 3) * 2;
            const float b0 = b3[cc], b1 = b3[cc + 1];
            *(uint32_t*)(C + r0 * 768 + cc) =
                packbf(acc[ma][na][0] + b0, acc[ma][na][1] + b1);
            *(uint32_t*)(C + (r0 + 8) * 768 + cc) =
                packbf(acc[ma][na][2] + b0, acc[ma][na][3] + b1);
        }
    }
}

// ---------------- fused flash attention + output projection (per-batch) ------
#define FSM (1024 + 196608)

__global__ void __launch_bounds__(256, 1)
flash_kernel(const bf16* __restrict__ qkv, const bf16* __restrict__ wpt,
             const float* __restrict__ bp, const float* __restrict__ x,
             const float* __restrict__ part, const float* __restrict__ gamma,
             const float* __restrict__ beta, float* __restrict__ out, int b)
{
    extern __shared__ char smraw[];
    const uint32_t base = (smem_u32(smraw) + 1023u) & ~1023u;
    const uint32_t Qs  = base;                 // 64KB Q
    const uint32_t Ks  = base + 65536u;        // 64KB K 2 stages
    const uint32_t Vs  = base + 131072u;       // 64KB V 2 stages
    const uint32_t Wps = base + 65536u;        // epilogue: Wp^T 128KB over K+V
    __shared__ float2 sstat[8];

    const int tid  = threadIdx.x;
    const int wid  = tid >> 5;
    const int lane = tid & 31;
    const int q0   = blockIdx.x * 128;
    const bf16* qp = qkv + (size_t)b * NTOK * 768;
    const bf16* kp = qp + 256;
    const bf16* vp = qp + 512;

    #pragma unroll
    for (int l = 0; l < 16; ++l) {
        const int f = tid + l * 256;
        const int r = f >> 5, pan = (f >> 3) & 3, ch = f & 7;
        cp16(Qs + pan * 16384u + swz((uint32_t)(r * 128 + ch * 16)),
             qp + (size_t)(q0 + r) * 768 + pan * 64 + ch * 8);
    }
    #pragma unroll
    for (int l = 0; l < 8; ++l) {
        const int f = tid + l * 256;
        const int r = f >> 5, pan = (f >> 3) & 3, ch = f & 7;
        const uint32_t so = (uint32_t)pan * 8192u + swz((uint32_t)(r * 128 + ch * 16));
        cp16(Ks + so, kp + (size_t)r * 768 + pan * 64 + ch * 8);
        cp16(Vs + so, vp + (size_t)r * 768 + pan * 64 + ch * 8);
    }
    cp_commit();

    // GN stats for epilogue residual (overlapped with prologue loads)
    compute_stats(part, b, wid, lane, sstat);

    const int l15  = lane & 15;
    const int arow = wid * 16 + l15;
    const int colb = (lane >> 4) * 16;
    const int keyl = ((lane >> 3) & 1) * 8 + (lane & 7);
    const int dl8  = (lane >> 4) * 8;

    float acc_o[32][4];
    #pragma unroll
    for (int n = 0; n < 32; ++n)
        #pragma unroll
        for (int q = 0; q < 4; ++q) acc_o[n][q] = 0.f;
    float l0 = 0.f, l1 = 0.f;

    const int NBLK = NTOK / 64;
    for (int j = 0; j < NBLK; ++j) {
        const uint32_t st = (uint32_t)(j & 1) * 32768u;

        __syncthreads();   // stage (j+1)&1 fully consumed (iter j-1)
        if (j + 1 < NBLK) {
            const uint32_t stn = (uint32_t)((j + 1) & 1) * 32768u;
            const int key0 = (j + 1) * 64;
            #pragma unroll
            for (int l = 0; l < 8; ++l) {
                const int f = tid + l * 256;
                const int r = f >> 5, pan = (f >> 3) & 3, ch = f & 7;
                const uint32_t so = (uint32_t)pan * 8192u +
                                    swz((uint32_t)(r * 128 + ch * 16));
                cp16(Ks + stn + so, kp + (size_t)(key0 + r) * 768 + pan * 64 + ch * 8);
                cp16(Vs + stn + so, vp + (size_t)(key0 + r) * 768 + pan * 64 + ch * 8);
            }
            cp_commit();
            cp_wait1();
        } else {
            cp_wait0();
        }

        // ---- S = Q @ K^T ----
        float s[8][4];
        #pragma unroll
        for (int n = 0; n < 8; ++n)
            #pragma unroll
            for (int q = 0; q < 4; ++q) s[n][q] = 0.f;

        #pragma unroll
        for (int pan = 0; pan < 4; ++pan) {
            const uint32_t qb = Qs + (uint32_t)pan * 16384u;
            const uint32_t kb = Ks + st + (uint32_t)pan * 8192u;
            #pragma unroll
            for (int kst = 0; kst < 4; ++kst) {
                const uint32_t kby = (uint32_t)(kst * 32 + colb);
                uint32_t afr[4], bfr[4][4];
                LDM4(afr, qb + swz((uint32_t)arow * 128 + kby));
                #pragma unroll
                for (int nb2 = 0; nb2 < 4; ++nb2)
                    LDM4(bfr[nb2], kb + swz((uint32_t)(l15 + nb2 * 16) * 128 + kby));
                #pragma unroll
                for (int nb2 = 0; nb2 < 4; ++nb2) {
                    mma_bf16(s[nb2 * 2],     afr, bfr[nb2][0], bfr[nb2][2]);
                    mma_bf16(s[nb2 * 2 + 1], afr, bfr[nb2][1], bfr[nb2][3]);
                }
            }
        }

        // ---- p = exp2(s) (log2e pre-folded), accumulate row sums ----
        float ps0 = 0.f, ps1 = 0.f;
        #pragma unroll
        for (int n = 0; n < 8; ++n) {
            s[n][0] = ex2(s[n][0]);
            s[n][1] = ex2(s[n][1]);
            s[n][2] = ex2(s[n][2]);
            s[n][3] = ex2(s[n][3]);
            ps0 += s[n][0] + s[n][1];
            ps1 += s[n][2] + s[n][3];
        }
        l0 += ps0;
        l1 += ps1;

        // ---- O += P @ V ----
        #pragma unroll
        for (int kk = 0; kk < 4; ++kk) {
            uint32_t a[4];
            a[0] = packbf(s[2 * kk][0],     s[2 * kk][1]);
            a[1] = packbf(s[2 * kk][2],     s[2 * kk][3]);
            a[2] = packbf(s[2 * kk + 1][0], s[2 * kk + 1][1]);
            a[3] = packbf(s[2 * kk + 1][2], s[2 * kk + 1][3]);
            const int key = kk * 16 + keyl;
            #pragma unroll
            for (int dg = 0; dg < 8; ++dg) {
                const int d0 = dg * 16 + dl8;
                uint32_t vfr[4];
                LDM4T(vfr, Vs + st + (uint32_t)(d0 >> 6) * 8192u +
                           swz((uint32_t)(key * 128 + (d0 & 63) * 2)));
                mma_bf16(acc_o[dg * 2],     a, vfr[0], vfr[1]);
                mma_bf16(acc_o[dg * 2 + 1], a, vfr[2], vfr[3]);
            }
        }
    }

    // ---- row-sum reduction ----
    l0 += __shfl_xor_sync(0xffffffffu, l0, 1);
    l0 += __shfl_xor_sync(0xffffffffu, l0, 2);
    l1 += __shfl_xor_sync(0xffffffffu, l1, 1);
    l1 += __shfl_xor_sync(0xffffffffu, l1, 2);
    const float i0 = 1.f / l0, i1 = 1.f / l1;

    __syncthreads();   // all warps done reading K/V smem of final iter

    // ---- stage Wp^T into dead K/V smem as 4 K-format 64x256 tiles ----
    #pragma unroll
    for (int l = 0; l < 32; ++l) {
        const int f  = tid + l * 256;     // 0..8191 16B chunks
        const int nb = f >> 11;           // 64-row block 0..3
        const int f2 = f & 2047;
        const int r = f2 >> 5, pan = (f2 >> 3) & 3, ch = f2 & 7;
        cp16(Wps + (uint32_t)nb * 32768u + (uint32_t)pan * 8192u +
                 swz((uint32_t)(r * 128 + ch * 16)),
             wpt + (size_t)(nb * 64 + r) * 256 + pan * 64 + ch * 8);
    }
    cp_commit();

    // ---- normalized O A-fragments direct from registers (P-trick layout) ----
    uint32_t oa[16][4];
    #pragma unroll
    for (int kst = 0; kst < 16; ++kst) {
        oa[kst][0] = packbf(acc_o[2 * kst][0] * i0,     acc_o[2 * kst][1] * i0);
        oa[kst][1] = packbf(acc_o[2 * kst][2] * i1,     acc_o[2 * kst][3] * i1);
        oa[kst][2] = packbf(acc_o[2 * kst + 1][0] * i0, acc_o[2 * kst + 1][1] * i0);
        oa[kst][3] = packbf(acc_o[2 * kst + 1][2] * i1, acc_o[2 * kst + 1][3] * i1);
    }
    cp_wait0();
    __syncthreads();   // Wp^T visible to all

    // ---- proj GEMM: each warp owns rows wid*16..+15, loops 4 col-blocks ----
    const int lr = wid * 16 + (lane >> 2);
    const size_t gr = (size_t)b * NTOK + q0 + lr;

    #pragma unroll
    for (int nbq = 0; nbq < 4; ++nbq) {
        const uint32_t wb = Wps + (uint32_t)nbq * 32768u;
        float pa[8][4];
        #pragma unroll
        for (int j = 0; j < 8; j++)
            #pragma unroll
            for (int q = 0; q < 4; q++) pa[j][q] = 0.f;

        #pragma unroll
        for (int kst = 0; kst < 16; ++kst) {
            const uint32_t pan = (uint32_t)(kst >> 2);
            const uint32_t kby = (uint32_t)((kst & 3) * 32 + colb);
            uint32_t bfr[4][4];
            #pragma unroll
            for (int nb2 = 0; nb2 < 4; ++nb2)
                LDM4(bfr[nb2], wb + pan * 8192u +
                               swz((uint32_t)(l15 + nb2 * 16) * 128 + kby));
            #pragma unroll
            for (int nb2 = 0; nb2 < 4; ++nb2) {
                mma_bf16(pa[nb2 * 2],     oa[kst], bfr[nb2][0], bfr[nb2][2]);
                mma_bf16(pa[nb2 * 2 + 1], oa[kst], bfr[nb2][1], bfr[nb2][3]);
            }
        }

        // epilogue: bias + GroupNorm residual (stats from smem), fp32 out
        #pragma unroll
        for (int na = 0; na < 8; ++na) {
            const int cc = nbq * 64 + (na >> 1) * 16 + (na & 1) * 8 +
                           (lane & 3) * 2;
            const float2 st = sstat[cc >> 5];
            const float gm0 = gamma[cc], gm1 = gamma[cc + 1];
            const float bt0 = beta[cc],  bt1 = beta[cc + 1];
            const float b0 = bp[cc], b1 = bp[cc + 1];
            float2 xv0 = *(const float2*)&x[gr * 256 + cc];
            float2 xv1 = *(const float2*)&x[(gr + 8) * 256 + cc];
            float v0 = pa[na][0] + b0 + (xv0.x - st.x) * st.y * gm0 + bt0;
            float v1 = pa[na][1] + b1 + (xv0.y - st.x) * st.y * gm1 + bt1;
            float v2 = pa[na][2] + b0 + (xv1.x - st.x) * st.y * gm0 + bt0;
            float v3 = pa[na][3] + b1 + (xv1.y - st.x) * st.y * gm1 + bt1;
            *(float2*)(out + gr * 256 + cc)       = make_float2(v0, v1);
            *(float2*)(out + (gr + 8) * 256 + cc) = make_float2(v2, v3);
        }
    }
}

// ---------------- static streams/events for capture-fork ---------------------
// Created once at load time (host objects only; no device memory). Reused
// every call so kernel_launch performs identical work on every invocation.
struct GStreams {
    cudaStream_t s[3];
    cudaEvent_t  evP, evB[3];
    GStreams() {
        for (int i = 0; i < 3; ++i)
            cudaStreamCreateWithFlags(&s[i], cudaStreamNonBlocking);
        cudaEventCreateWithFlags(&evP, cudaEventDisableTiming);
        for (int i = 0; i < 3; ++i)
            cudaEventCreateWithFlags(&evB[i], cudaEventDisableTiming);
    }
};
static GStreams g_str;

// ---------------- launch ------------------------------------------------------
extern "C" void kernel_launch(void* const* d_in, const int* in_sizes, int n_in,
                              void* d_out, int out_size)
{
    const float* x     = (const float*)d_in[0];
    const float* gamma = (const float*)d_in[1];
    const float* beta  = (const float*)d_in[2];
    const float* Wq    = (const float*)d_in[3];
    const float* bq    = (const float*)d_in[4];
    const float* Wk    = (const float*)d_in[5];
    const float* bk    = (const float*)d_in[6];
    const float* Wv    = (const float*)d_in[7];
    const float* bv    = (const float*)d_in[8];
    const float* Wp    = (const float*)d_in[9];
    const float* bp    = (const float*)d_in[10];
    float* out = (float*)d_out;

    float *b3, *part;  bf16 *qkv, *wt, *wpt;
    cudaGetSymbolAddress((void**)&qkv,  g_qkv);
    cudaGetSymbolAddress((void**)&wt,   g_wt);
    cudaGetSymbolAddress((void**)&wpt,  g_wpt);
    cudaGetSymbolAddress((void**)&b3,   g_b3);
    cudaGetSymbolAddress((void**)&part, g_part);

    cudaFuncSetAttribute(qkv_gemm,     cudaFuncAttributeMaxDynamicSharedMemorySize, QSM);
    cudaFuncSetAttribute(flash_kernel, cudaFuncAttributeMaxDynamicSharedMemorySize, FSM);

    // 1) weight prep + GN partial sums (merged), on the captured stream
    prep_gn_kernel<<<1280, 256>>>(Wq, Wk, Wv, Wp, wt, wpt, bq, bk, bv, b3,
                                  x, part);
    cudaEventRecord(g_str.evP, 0);
    for (int i = 0; i < 3; ++i)
        cudaStreamWaitEvent(g_str.s[i], g_str.evP, 0);

    // 2+3) per-batch qkv -> flash pipelines; batch 0 on the captured stream,
    // batches 1-3 forked onto side streams (overlaps qkv(b>0) with flash(b0)).
    qkv_gemm<<<dim3(6, 32), 256, QSM>>>(x, gamma, beta, part, wt, b3, qkv, 0);
    flash_kernel<<<32, 256, FSM>>>(qkv, wpt, bp, x, part, gamma, beta, out, 0);
    for (int i = 0; i < 3; ++i) {
        const int b = i + 1;
        qkv_gemm<<<dim3(6, 32), 256, QSM, g_str.s[i]>>>(
            x, gamma, beta, part, wt, b3, qkv, b);
        flash_kernel<<<32, 256, FSM, g_str.s[i]>>>(
            qkv, wpt, bp, x, part, gamma, beta, out, b);
        cudaEventRecord(g_str.evB[i], g_str.s[i]);
    }
    for (int i = 0; i < 3; ++i)
        cudaStreamWaitEvent(0, g_str.evB[i], 0);
}

// round 16
// speedup vs baseline: 1.0491x; 1.0098x over previous
#include <cuda_runtime.h>
#include <cuda_bf16.h>
#include <cstdint>
#include <cstddef>

using bf16  = __nv_bfloat16;
using bf162 = __nv_bfloat162;

#define BATCH  4
#define NTOK   4096
#define CDIM   256
#define GROUPS 8
#define EPSV   1e-3f
#define GNM    131072.0f     // elements per (b,g) group

// q pre-scale: (1/16 softmax scale) * log2(e) so exp(x) == exp2(s)
#define QSCALE 0.09016843806266f

// ---------------- static device scratch (no cudaMalloc) ---------------------
__device__ bf16  g_qkv  [(size_t)BATCH * NTOK * 3 * CDIM];
__device__ bf16  g_wt   [3 * CDIM * CDIM];
__device__ bf16  g_wpt  [CDIM * CDIM];
__device__ float g_b3   [3 * CDIM];
__device__ float g_part [BATCH * GROUPS * 64 * 2];  // partial sums (64 slabs)

// ---------------- helpers -----------------------------------------------------
__device__ __forceinline__ uint32_t smem_u32(const void* p) {
    uint32_t a;
    asm("{ .reg .u64 t; cvta.to.shared.u64 t, %1; cvt.u32.u64 %0, t; }"
        : "=r"(a) : "l"(p));
    return a;
}
__device__ __forceinline__ uint32_t swz(uint32_t b) { return b ^ ((b >> 3) & 0x70); }

#define LDM4(r, addr) \
    asm volatile("ldmatrix.sync.aligned.m8n8.x4.shared.b16 {%0,%1,%2,%3}, [%4];" \
        : "=r"((r)[0]), "=r"((r)[1]), "=r"((r)[2]), "=r"((r)[3]) : "r"(addr))
#define LDM4T(r, addr) \
    asm volatile("ldmatrix.sync.aligned.m8n8.x4.trans.shared.b16 {%0,%1,%2,%3}, [%4];" \
        : "=r"((r)[0]), "=r"((r)[1]), "=r"((r)[2]), "=r"((r)[3]) : "r"(addr))

__device__ __forceinline__ void mma_bf16(float* c, const uint32_t* a,
                                         uint32_t b0, uint32_t b1) {
    asm volatile(
        "mma.sync.aligned.m16n8k16.row.col.f32.bf16.bf16.f32 "
        "{%0,%1,%2,%3}, {%4,%5,%6,%7}, {%8,%9}, {%0,%1,%2,%3};"
        : "+f"(c[0]), "+f"(c[1]), "+f"(c[2]), "+f"(c[3])
        : "r"(a[0]), "r"(a[1]), "r"(a[2]), "r"(a[3]), "r"(b0), "r"(b1));
}

__device__ __forceinline__ void cp16(uint32_t saddr, const void* gaddr) {
    asm volatile("cp.async.cg.shared.global [%0], [%1], 16;"
                 :: "r"(saddr), "l"(gaddr));
}
__device__ __forceinline__ void cp_commit() {
    asm volatile("cp.async.commit_group;" ::: "memory");
}
__device__ __forceinline__ void cp_wait1() {
    asm volatile("cp.async.wait_group 1;" ::: "memory");
}
__device__ __forceinline__ void cp_wait0() {
    asm volatile("cp.async.wait_group 0;" ::: "memory");
}
__device__ __forceinline__ uint32_t packbf(float a, float b) {
    bf162 p = __floats2bfloat162_rn(a, b);
    return *(uint32_t*)&p;
}
__device__ __forceinline__ float ex2(float x) {
    float r;
    asm("ex2.approx.f32 %0, %1;" : "=f"(r) : "f"(x));
    return r;
}
__device__ __forceinline__ void sts64(uint32_t a, uint32_t v0, uint32_t v1) {
    asm volatile("st.shared.v2.b32 [%0], {%1,%2};" :: "r"(a), "r"(v0), "r"(v1));
}

// ---- per-CTA GroupNorm stats: 8 warps reduce 64 partials each -> sstat[8] ----
__device__ __forceinline__ void compute_stats(const float* __restrict__ part,
                                              int b, int wid, int lane,
                                              float2* sstat)
{
    const float* pg = part + (((b << 3) + wid) * 64) * 2;
    const float2 p0 = *(const float2*)&pg[lane * 2];
    const float2 p1 = *(const float2*)&pg[(lane + 32) * 2];
    float s = p0.x + p1.x, ss = p0.y + p1.y;
    #pragma unroll
    for (int o = 16; o; o >>= 1) {
        s  += __shfl_xor_sync(0xffffffffu, s,  o);
        ss += __shfl_xor_sync(0xffffffffu, ss, o);
    }
    if (lane == 0) {
        const float mean = s / GNM;
        sstat[wid] = make_float2(mean, rsqrtf(ss / GNM - mean * mean + EPSV));
    }
}

// ---------------- merged: weight prep (256 blocks) + GN partial (2048) -------
__global__ void __launch_bounds__(256)
prep_gn_kernel(const float* __restrict__ Wq, const float* __restrict__ Wk,
               const float* __restrict__ Wv, const float* __restrict__ Wp,
               bf16* __restrict__ wt, bf16* __restrict__ wpt,
               const float* __restrict__ bq, const float* __restrict__ bk,
               const float* __restrict__ bv, float* __restrict__ b3,
               const float* __restrict__ x, float* __restrict__ part)
{
    const int tid = threadIdx.x;
    if (blockIdx.x < 2048) {
        // ---- GN partial sums (64-row slabs, 2 indep loads per thread) ----
        const int bg = blockIdx.x >> 6, slab = blockIdx.x & 63;
        const int b = bg >> 3, g = bg & 7;
        const size_t base = (size_t)b * NTOK * CDIM + (size_t)g * 32 +
                            (size_t)(slab * 64) * CDIM;

        const int m0 = tid >> 3, qd = tid & 7;
        float4 v0 = *(const float4*)&x[base + (size_t)m0 * CDIM + qd * 4];
        float4 v1 = *(const float4*)&x[base + (size_t)(m0 + 32) * CDIM + qd * 4];
        float s  = (v0.x + v0.y) + (v0.z + v0.w) +
                   (v1.x + v1.y) + (v1.z + v1.w);
        float ss = (v0.x * v0.x + v0.y * v0.y + v0.z * v0.z + v0.w * v0.w) +
                   (v1.x * v1.x + v1.y * v1.y + v1.z * v1.z + v1.w * v1.w);

        #pragma unroll
        for (int o = 16; o; o >>= 1) {
            s  += __shfl_xor_sync(0xffffffffu, s,  o);
            ss += __shfl_xor_sync(0xffffffffu, ss, o);
        }
        __shared__ float shs[8], shss[8];
        if (!(tid & 31)) { shs[tid >> 5] = s; shss[tid >> 5] = ss; }
        __syncthreads();
        if (tid == 0) {
            float st = 0.f, sst = 0.f;
            #pragma unroll
            for (int i = 0; i < 8; i++) { st += shs[i]; sst += shss[i]; }
            part[blockIdx.x * 2]     = st;
            part[blockIdx.x * 2 + 1] = sst;
        }
    } else {
        // ---- weight transpose + convert ----
        const int idx = blockIdx.x - 2048;
        const int z = idx >> 6;
        const int bxq = (idx & 7) * 32, byq = ((idx >> 3) & 7) * 32;
        const float* W = (z == 0) ? Wq : (z == 1) ? Wk : (z == 2) ? Wv : Wp;
        bf16* out = (z < 3) ? (wt + (size_t)z * CDIM * CDIM) : wpt;
        const float scale = (z == 0) ? QSCALE : 1.0f;

        __shared__ float t[32][33];
        const int tx = tid & 31, ty = tid >> 5;
        for (int yy = ty; yy < 32; yy += 8)
            t[yy][tx] = W[(size_t)(byq + yy) * CDIM + bxq + tx];
        __syncthreads();
        for (int yy = ty; yy < 32; yy += 8)
            out[(size_t)(bxq + yy) * CDIM + byq + tx] =
                __float2bfloat16(t[tx][yy] * scale);

        if (z == 3 && idx == 192) {   // z==3, x==0, y==0
            for (int j = tid; j < 768; j += 256)
                b3[j] = (j < 256) ? bq[j] * QSCALE
                      : (j < 512) ? bk[j - 256] : bv[j - 512];
        }
    }
}

// ---------------- QKV GEMM with inline GroupNorm on A (per-batch grid) -------
#define QSM (1024 + 65536 + 32768)

__device__ __forceinline__ void cpb_tile(uint32_t sdst,
    const bf16* __restrict__ g, int row0, int k0, int tid)
{
    #pragma unroll
    for (int l = 0; l < 4; ++l) {
        const int f = tid + l * 256;
        const int r = f >> 3;
        const int q = f & 7;
        cp16(sdst + swz((uint32_t)(r * 128 + q * 16)),
             g + (size_t)(row0 + r) * 256 + k0 + q * 8);
    }
}

__global__ void __launch_bounds__(256)
qkv_gemm(const float* __restrict__ x, const float* __restrict__ gamma,
         const float* __restrict__ beta, const float* __restrict__ part,
         const bf16* __restrict__ wt, const float* __restrict__ b3,
         bf16* __restrict__ C, int batch)
{
    extern __shared__ char smraw[];
    const uint32_t base = (smem_u32(smraw) + 1023u) & ~1023u;
    const uint32_t As = base;              // 64KB: 4 panels of 128x64 cols
    const uint32_t Bs = base + 65536u;     // 2x16KB B double buffer
    __shared__ float2 sstat[8];

    const int tid  = threadIdx.x;
    const int wid  = tid >> 5;
    const int lane = tid & 31;
    const int wm   = wid & 3;
    const int wn   = wid >> 2;
    const int row0 = batch * NTOK + blockIdx.y * 128;
    const int b    = batch;
    const int col0 = blockIdx.x * 128;

    compute_stats(part, b, wid, lane, sstat);
    cpb_tile(Bs, wt, col0, 0, tid);
    cp_commit();
    __syncthreads();   // sstat visible

    // A: load x fp32, normalize, pack bf16, store to panel-format smem
    #pragma unroll
    for (int l = 0; l < 32; ++l) {
        const int f  = tid + l * 256;
        const int r  = f >> 6;
        const int c4 = f & 63;
        float4 xv = *(const float4*)&x[(size_t)(row0 + r) * 256 + c4 * 4];
        float4 gm = *(const float4*)&gamma[c4 * 4];
        float4 bt = *(const float4*)&beta [c4 * 4];
        const float2 st = sstat[c4 >> 3];
        const uint32_t u0 = packbf((xv.x - st.x) * st.y * gm.x + bt.x,
                                   (xv.y - st.x) * st.y * gm.y + bt.y);
        const uint32_t u1 = packbf((xv.z - st.x) * st.y * gm.z + bt.z,
                                   (xv.w - st.x) * st.y * gm.w + bt.w);
        sts64(As + (uint32_t)(c4 >> 4) * 16384u +
                  swz((uint32_t)(r * 128 + (c4 & 15) * 8)), u0, u1);
    }

    const int arow  = wm * 32 + (lane & 15);
    const int brow  = wn * 64 + (lane & 15);
    const int colb  = (lane >> 4) * 16;

    float acc[2][8][4];
    #pragma unroll
    for (int i = 0; i < 2; i++)
        #pragma unroll
        for (int j = 0; j < 8; j++)
            #pragma unroll
            for (int q = 0; q < 4; q++) acc[i][j][q] = 0.f;

    for (int i = 0; i < 4; ++i) {
        if (i + 1 < 4) {
            cpb_tile(Bs + (uint32_t)((i + 1) & 1) * 16384u,
                     wt, col0, (i + 1) * 64, tid);
            cp_commit();
            cp_wait1();
        } else {
            cp_wait0();
        }
        __syncthreads();

        const uint32_t ap = As + (uint32_t)i * 16384u;
        const uint32_t bb = Bs + (uint32_t)(i & 1) * 16384u;
        #pragma unroll
        for (int kst = 0; kst < 4; ++kst) {
            const uint32_t kb = (uint32_t)(kst * 32 + colb);
            uint32_t afr[2][4], bfr[4][4];
            LDM4(afr[0], ap + swz((uint32_t)(arow)      * 128 + kb));
            LDM4(afr[1], ap + swz((uint32_t)(arow + 16) * 128 + kb));
            #pragma unroll
            for (int nb2 = 0; nb2 < 4; ++nb2)
                LDM4(bfr[nb2], bb + swz((uint32_t)(brow + nb2 * 16) * 128 + kb));
            #pragma unroll
            for (int ma = 0; ma < 2; ++ma)
                #pragma unroll
                for (int nb2 = 0; nb2 < 4; ++nb2) {
                    mma_bf16(acc[ma][nb2 * 2],     afr[ma], bfr[nb2][0], bfr[nb2][2]);
                    mma_bf16(acc[ma][nb2 * 2 + 1], afr[ma], bfr[nb2][1], bfr[nb2][3]);
                }
        }
        __syncthreads();
    }

    #pragma unroll
    for (int ma = 0; ma < 2; ++ma) {
        const size_t r0 = (size_t)(row0 + wm * 32 + ma * 16 + (lane >> 2));
        #pragma unroll
        for (int na = 0; na < 8; ++na) {
            const int cc = col0 + wn * 64 + (na >> 1) * 16 + (na & 1) * 8 +
                           (lane & 3) * 2;
            const float b0 = b3[cc], b1 = b3[cc + 1];
            *(uint32_t*)(C + r0 * 768 + cc) =
                packbf(acc[ma][na][0] + b0, acc[ma][na][1] + b1);
            *(uint32_t*)(C + (r0 + 8) * 768 + cc) =
                packbf(acc[ma][na][2] + b0, acc[ma][na][3] + b1);
        }
    }
}

// ---------------- fused flash attention + output projection (per-batch) ------
#define FSM (1024 + 196608)

__global__ void __launch_bounds__(256, 1)
flash_kernel(const bf16* __restrict__ qkv, const bf16* __restrict__ wpt,
             const float* __restrict__ bp, const float* __restrict__ x,
             const float* __restrict__ part, const float* __restrict__ gamma,
             const float* __restrict__ beta, float* __restrict__ out, int b)
{
    extern __shared__ char smraw[];
    const uint32_t base = (smem_u32(smraw) + 1023u) & ~1023u;
    const uint32_t Qs  = base;                 // 64KB Q
    const uint32_t Ks  = base + 65536u;        // 64KB K 2 stages
    const uint32_t Vs  = base + 131072u;       // 64KB V 2 stages
    const uint32_t Wps = base + 65536u;        // epilogue: Wp^T 128KB over K+V
    __shared__ float2 sstat[8];

    const int tid  = threadIdx.x;
    const int wid  = tid >> 5;
    const int lane = tid & 31;
    const int q0   = blockIdx.x * 128;
    const bf16* qp = qkv + (size_t)b * NTOK * 768;
    const bf16* kp = qp + 256;
    const bf16* vp = qp + 512;

    #pragma unroll
    for (int l = 0; l < 16; ++l) {
        const int f = tid + l * 256;
        const int r = f >> 5, pan = (f >> 3) & 3, ch = f & 7;
        cp16(Qs + pan * 16384u + swz((uint32_t)(r * 128 + ch * 16)),
             qp + (size_t)(q0 + r) * 768 + pan * 64 + ch * 8);
    }
    #pragma unroll
    for (int l = 0; l < 8; ++l) {
        const int f = tid + l * 256;
        const int r = f >> 5, pan = (f >> 3) & 3, ch = f & 7;
        const uint32_t so = (uint32_t)pan * 8192u + swz((uint32_t)(r * 128 + ch * 16));
        cp16(Ks + so, kp + (size_t)r * 768 + pan * 64 + ch * 8);
        cp16(Vs + so, vp + (size_t)r * 768 + pan * 64 + ch * 8);
    }
    cp_commit();

    // GN stats for epilogue residual (overlapped with prologue loads)
    compute_stats(part, b, wid, lane, sstat);

    const int l15  = lane & 15;
    const int arow = wid * 16 + l15;
    const int colb = (lane >> 4) * 16;
    const int keyl = ((lane >> 3) & 1) * 8 + (lane & 7);
    const int dl8  = (lane >> 4) * 8;

    float acc_o[32][4];
    #pragma unroll
    for (int n = 0; n < 32; ++n)
        #pragma unroll
        for (int q = 0; q < 4; ++q) acc_o[n][q] = 0.f;
    float l0 = 0.f, l1 = 0.f;

    const int NBLK = NTOK / 64;
    for (int j = 0; j < NBLK; ++j) {
        const uint32_t st = (uint32_t)(j & 1) * 32768u;

        __syncthreads();   // stage (j+1)&1 fully consumed (iter j-1)
        if (j + 1 < NBLK) {
            const uint32_t stn = (uint32_t)((j + 1) & 1) * 32768u;
            const int key0 = (j + 1) * 64;
            #pragma unroll
            for (int l = 0; l < 8; ++l) {
                const int f = tid + l * 256;
                const int r = f >> 5, pan = (f >> 3) & 3, ch = f & 7;
                const uint32_t so = (uint32_t)pan * 8192u +
                                    swz((uint32_t)(r * 128 + ch * 16));
                cp16(Ks + stn + so, kp + (size_t)(key0 + r) * 768 + pan * 64 + ch * 8);
                cp16(Vs + stn + so, vp + (size_t)(key0 + r) * 768 + pan * 64 + ch * 8);
            }
            cp_commit();
            cp_wait1();
        } else {
            cp_wait0();
        }

        // ---- S = Q @ K^T ----
        float s[8][4];
        #pragma unroll
        for (int n = 0; n < 8; ++n)
            #pragma unroll
            for (int q = 0; q < 4; ++q) s[n][q] = 0.f;

        #pragma unroll
        for (int pan = 0; pan < 4; ++pan) {
            const uint32_t qb = Qs + (uint32_t)pan * 16384u;
            const uint32_t kb = Ks + st + (uint32_t)pan * 8192u;
            #pragma unroll
            for (int kst = 0; kst < 4; ++kst) {
                const uint32_t kby = (uint32_t)(kst * 32 + colb);
                uint32_t afr[4], bfr[4][4];
                LDM4(afr, qb + swz((uint32_t)arow * 128 + kby));
                #pragma unroll
                for (int nb2 = 0; nb2 < 4; ++nb2)
                    LDM4(bfr[nb2], kb + swz((uint32_t)(l15 + nb2 * 16) * 128 + kby));
                #pragma unroll
                for (int nb2 = 0; nb2 < 4; ++nb2) {
                    mma_bf16(s[nb2 * 2],     afr, bfr[nb2][0], bfr[nb2][2]);
                    mma_bf16(s[nb2 * 2 + 1], afr, bfr[nb2][1], bfr[nb2][3]);
                }
            }
        }

        // ---- p = exp2(s) (log2e pre-folded), accumulate row sums ----
        float ps0 = 0.f, ps1 = 0.f;
        #pragma unroll
        for (int n = 0; n < 8; ++n) {
            s[n][0] = ex2(s[n][0]);
            s[n][1] = ex2(s[n][1]);
            s[n][2] = ex2(s[n][2]);
            s[n][3] = ex2(s[n][3]);
            ps0 += s[n][0] + s[n][1];
            ps1 += s[n][2] + s[n][3];
        }
        l0 += ps0;
        l1 += ps1;

        // ---- O += P @ V ----
        #pragma unroll
        for (int kk = 0; kk < 4; ++kk) {
            uint32_t a[4];
            a[0] = packbf(s[2 * kk][0],     s[2 * kk][1]);
            a[1] = packbf(s[2 * kk][2],     s[2 * kk][3]);
            a[2] = packbf(s[2 * kk + 1][0], s[2 * kk + 1][1]);
            a[3] = packbf(s[2 * kk + 1][2], s[2 * kk + 1][3]);
            const int key = kk * 16 + keyl;
            #pragma unroll
            for (int dg = 0; dg < 8; ++dg) {
                const int d0 = dg * 16 + dl8;
                uint32_t vfr[4];
                LDM4T(vfr, Vs + st + (uint32_t)(d0 >> 6) * 8192u +
                           swz((uint32_t)(key * 128 + (d0 & 63) * 2)));
                mma_bf16(acc_o[dg * 2],     a, vfr[0], vfr[1]);
                mma_bf16(acc_o[dg * 2 + 1], a, vfr[2], vfr[3]);
            }
        }
    }

    // ---- row-sum reduction ----
    l0 += __shfl_xor_sync(0xffffffffu, l0, 1);
    l0 += __shfl_xor_sync(0xffffffffu, l0, 2);
    l1 += __shfl_xor_sync(0xffffffffu, l1, 1);
    l1 += __shfl_xor_sync(0xffffffffu, l1, 2);
    const float i0 = 1.f / l0, i1 = 1.f / l1;

    __syncthreads();   // all warps done reading K/V smem of final iter

    // ---- stage Wp^T into dead K/V smem as 4 K-format 64x256 tiles ----
    #pragma unroll
    for (int l = 0; l < 32; ++l) {
        const int f  = tid + l * 256;     // 0..8191 16B chunks
        const int nb = f >> 11;           // 64-row block 0..3
        const int f2 = f & 2047;
        const int r = f2 >> 5, pan = (f2 >> 3) & 3, ch = f2 & 7;
        cp16(Wps + (uint32_t)nb * 32768u + (uint32_t)pan * 8192u +
                 swz((uint32_t)(r * 128 + ch * 16)),
             wpt + (size_t)(nb * 64 + r) * 256 + pan * 64 + ch * 8);
    }
    cp_commit();

    // ---- normalized O A-fragments direct from registers (P-trick layout) ----
    uint32_t oa[16][4];
    #pragma unroll
    for (int kst = 0; kst < 16; ++kst) {
        oa[kst][0] = packbf(acc_o[2 * kst][0] * i0,     acc_o[2 * kst][1] * i0);
        oa[kst][1] = packbf(acc_o[2 * kst][2] * i1,     acc_o[2 * kst][3] * i1);
        oa[kst][2] = packbf(acc_o[2 * kst + 1][0] * i0, acc_o[2 * kst + 1][1] * i0);
        oa[kst][3] = packbf(acc_o[2 * kst + 1][2] * i1, acc_o[2 * kst + 1][3] * i1);
    }
    cp_wait0();
    __syncthreads();   // Wp^T visible to all

    // ---- proj GEMM: each warp owns rows wid*16..+15, loops 4 col-blocks ----
    const int lr = wid * 16 + (lane >> 2);
    const size_t gr = (size_t)b * NTOK + q0 + lr;

    #pragma unroll
    for (int nbq = 0; nbq < 4; ++nbq) {
        const uint32_t wb = Wps + (uint32_t)nbq * 32768u;
        float pa[8][4];
        #pragma unroll
        for (int j = 0; j < 8; j++)
            #pragma unroll
            for (int q = 0; q < 4; q++) pa[j][q] = 0.f;

        #pragma unroll
        for (int kst = 0; kst < 16; ++kst) {
            const uint32_t pan = (uint32_t)(kst >> 2);
            const uint32_t kby = (uint32_t)((kst & 3) * 32 + colb);
            uint32_t bfr[4][4];
            #pragma unroll
            for (int nb2 = 0; nb2 < 4; ++nb2)
                LDM4(bfr[nb2], wb + pan * 8192u +
                               swz((uint32_t)(l15 + nb2 * 16) * 128 + kby));
            #pragma unroll
            for (int nb2 = 0; nb2 < 4; ++nb2) {
                mma_bf16(pa[nb2 * 2],     oa[kst], bfr[nb2][0], bfr[nb2][2]);
                mma_bf16(pa[nb2 * 2 + 1], oa[kst], bfr[nb2][1], bfr[nb2][3]);
            }
        }

        // epilogue: bias + GroupNorm residual (stats from smem), fp32 out
        #pragma unroll
        for (int na = 0; na < 8; ++na) {
            const int cc = nbq * 64 + (na >> 1) * 16 + (na & 1) * 8 +
                           (lane & 3) * 2;
            const float2 st = sstat[cc >> 5];
            const float gm0 = gamma[cc], gm1 = gamma[cc + 1];
            const float bt0 = beta[cc],  bt1 = beta[cc + 1];
            const float b0 = bp[cc], b1 = bp[cc + 1];
            float2 xv0 = *(const float2*)&x[gr * 256 + cc];
            float2 xv1 = *(const float2*)&x[(gr + 8) * 256 + cc];
            float v0 = pa[na][0] + b0 + (xv0.x - st.x) * st.y * gm0 + bt0;
            float v1 = pa[na][1] + b1 + (xv0.y - st.x) * st.y * gm1 + bt1;
            float v2 = pa[na][2] + b0 + (xv1.x - st.x) * st.y * gm0 + bt0;
            float v3 = pa[na][3] + b1 + (xv1.y - st.x) * st.y * gm1 + bt1;
            *(float2*)(out + gr * 256 + cc)       = make_float2(v0, v1);
            *(float2*)(out + (gr + 8) * 256 + cc) = make_float2(v2, v3);
        }
    }
}

// ---------------- static streams/events for capture-fork ---------------------
struct GStreams {
    cudaStream_t s[3];
    cudaEvent_t  evP, evB[3];
    GStreams() {
        for (int i = 0; i < 3; ++i)
            cudaStreamCreateWithFlags(&s[i], cudaStreamNonBlocking);
        cudaEventCreateWithFlags(&evP, cudaEventDisableTiming);
        for (int i = 0; i < 3; ++i)
            cudaEventCreateWithFlags(&evB[i], cudaEventDisableTiming);
    }
};
static GStreams g_str;

// ---------------- launch ------------------------------------------------------
extern "C" void kernel_launch(void* const* d_in, const int* in_sizes, int n_in,
                              void* d_out, int out_size)
{
    const float* x     = (const float*)d_in[0];
    const float* gamma = (const float*)d_in[1];
    const float* beta  = (const float*)d_in[2];
    const float* Wq    = (const float*)d_in[3];
    const float* bq    = (const float*)d_in[4];
    const float* Wk    = (const float*)d_in[5];
    const float* bk    = (const float*)d_in[6];
    const float* Wv    = (const float*)d_in[7];
    const float* bv    = (const float*)d_in[8];
    const float* Wp    = (const float*)d_in[9];
    const float* bp    = (const float*)d_in[10];
    float* out = (float*)d_out;

    float *b3, *part;  bf16 *qkv, *wt, *wpt;
    cudaGetSymbolAddress((void**)&qkv,  g_qkv);
    cudaGetSymbolAddress((void**)&wt,   g_wt);
    cudaGetSymbolAddress((void**)&wpt,  g_wpt);
    cudaGetSymbolAddress((void**)&b3,   g_b3);
    cudaGetSymbolAddress((void**)&part, g_part);

    cudaFuncSetAttribute(qkv_gemm,     cudaFuncAttributeMaxDynamicSharedMemorySize, QSM);
    cudaFuncSetAttribute(flash_kernel, cudaFuncAttributeMaxDynamicSharedMemorySize, FSM);

    // 1) weight prep + GN partial sums (merged), on the captured stream
    prep_gn_kernel<<<2304, 256>>>(Wq, Wk, Wv, Wp, wt, wpt, bq, bk, bv, b3,
                                  x, part);
    cudaEventRecord(g_str.evP, 0);
    for (int i = 0; i < 3; ++i)
        cudaStreamWaitEvent(g_str.s[i], g_str.evP, 0);

    // 2+3) per-batch qkv -> flash pipelines; batch 0 on the captured stream,
    // batches 1-3 forked onto side streams.
    qkv_gemm<<<dim3(6, 32), 256, QSM>>>(x, gamma, beta, part, wt, b3, qkv, 0);
    flash_kernel<<<32, 256, FSM>>>(qkv, wpt, bp, x, part, gamma, beta, out, 0);
    for (int i = 0; i < 3; ++i) {
        const int b = i + 1;
        qkv_gemm<<<dim3(6, 32), 256, QSM, g_str.s[i]>>>(
            x, gamma, beta, part, wt, b3, qkv, b);
        flash_kernel<<<32, 256, FSM, g_str.s[i]>>>(
            qkv, wpt, bp, x, part, gamma, beta, out, b);
        cudaEventRecord(g_str.evB[i], g_str.s[i]);
    }
    for (int i = 0; i < 3; ++i)
        cudaStreamWaitEvent(0, g_str.evB[i], 0);
}